// round 8
// baseline (speedup 1.0000x reference)
#include <cuda_runtime.h>
#include <cstdint>

#define OMEGA_W 0.9f

#define N0 2048
#define N1 1024
#define N2 512
#define N3 256

// Scratch (device globals — no allocation allowed).
__device__ float g_u0b[N0 * N0];
__device__ float g_u0c[N0 * N0];
__device__ float g_u1a[N1 * N1];
__device__ float g_u1b[N1 * N1];
__device__ float g_r1[N1 * N1];
__device__ float g_u2a[N2 * N2];
__device__ float g_u2b[N2 * N2];
__device__ float g_r2[N2 * N2];
__device__ float g_u3a[N3 * N3];
__device__ float g_u3b[N3 * N3];
__device__ float g_r3[N3 * N3];

// Software grid-barrier ticket counter (monotonic; replay-safe under graphs).
__device__ unsigned int g_bar = 0;

// ---------------------------------------------------------------------------
// Grid-wide barrier for a co-resident grid of NCTAS CTAs.
// Writer side: __threadfence before arrive. Reader side: fence after wait.
// ---------------------------------------------------------------------------
__device__ __forceinline__ void grid_barrier_256() {
    __syncthreads();
    __threadfence();
    if (threadIdx.x == 0) {
        unsigned ticket = atomicAdd(&g_bar, 1u);
        unsigned target = (ticket / 256u + 1u) * 256u;
        while (*(volatile unsigned*)&g_bar < target) __nanosleep(64);
    }
    __syncthreads();
    __threadfence();
}

// ---------------------------------------------------------------------------
// One Jacobi update at a global point (global-memory reads).
// ---------------------------------------------------------------------------
__device__ __forceinline__ float jac_pt(const float* __restrict__ u,
                                        const float* __restrict__ rhs,
                                        const float* __restrict__ cx,
                                        const float* __restrict__ cy,
                                        int gy, int gx, int n, float ih2) {
    int idx = gy * n + gx;
    float um = u[idx];
    float ue = (gx + 1 < n) ? u[idx + 1] : 0.0f;
    float uw = (gx > 0) ? u[idx - 1] : 0.0f;
    float uN = (gy + 1 < n) ? u[idx + n] : 0.0f;
    float uS = (gy > 0) ? u[idx - n] : 0.0f;
    float cxe = cx[idx];
    float cxw = (gx > 0) ? cx[idx - 1] : 0.0f;
    float cyn = cy[idx];
    float cys = (gy > 0) ? cy[idx - n] : 0.0f;
    float lap = (cxe * (ue - um) - cxw * (um - uw)) * ih2 +
                (cyn * (uN - um) - cys * (um - uS)) * ih2;
    float r = rhs[idx] - (lap - um);
    float diag = -((cxe + cxw) + (cyn + cys)) * ih2 - 1.0f;
    return um + __fdividef(OMEGA_W * r, diag);
}

// ---------------------------------------------------------------------------
// One Jacobi update from an SMEM u-tile (coeffs from global).
// ---------------------------------------------------------------------------
__device__ __forceinline__ float jac_sm(const float* __restrict__ sm,
                                        int ly, int lx, int stride,
                                        const float* __restrict__ rhs,
                                        const float* __restrict__ cx,
                                        const float* __restrict__ cy,
                                        int gy, int gx, int n, float ih2) {
    int lp = ly * stride + lx;
    float um = sm[lp];
    float ue = sm[lp + 1];
    float uw = sm[lp - 1];
    float uN = sm[lp + stride];
    float uS = sm[lp - stride];
    int idx = gy * n + gx;
    float cxe = cx[idx];
    float cxw = (gx > 0) ? cx[idx - 1] : 0.0f;
    float cyn = cy[idx];
    float cys = (gy > 0) ? cy[idx - n] : 0.0f;
    float lap = (cxe * (ue - um) - cxw * (um - uw)) * ih2 +
                (cyn * (uN - um) - cys * (um - uS)) * ih2;
    float r = rhs[idx] - (lap - um);
    float diag = -((cxe + cxw) + (cyn + cys)) * ih2 - 1.0f;
    return um + __fdividef(OMEGA_W * r, diag);
}

// ---------------------------------------------------------------------------
// Residual from an SMEM u-tile.
// ---------------------------------------------------------------------------
__device__ __forceinline__ float resid_sm(const float* __restrict__ sm,
                                          int ly, int lx, int stride,
                                          const float* __restrict__ rhs,
                                          const float* __restrict__ cx,
                                          const float* __restrict__ cy,
                                          int gy, int gx, int n, float ih2) {
    int lp = ly * stride + lx;
    float um = sm[lp];
    float ue = sm[lp + 1];
    float uw = sm[lp - 1];
    float uN = sm[lp + stride];
    float uS = sm[lp - stride];
    int idx = gy * n + gx;
    float cxe = cx[idx];
    float cxw = (gx > 0) ? cx[idx - 1] : 0.0f;
    float cyn = cy[idx];
    float cys = (gy > 0) ? cy[idx - n] : 0.0f;
    float lap = (cxe * (ue - um) - cxw * (um - uw)) * ih2 +
                (cyn * (uN - um) - cys * (um - uS)) * ih2;
    return rhs[idx] - (lap - um);
}

// ===========================================================================
// Tile bodies as device functions (1-D 256-thread block, tile 64x16).
// pool must hold >= 2548 floats: s1 = pool[0..1360), su = pool[1360..2548).
// ===========================================================================
__device__ void jrr0_tile(const float* __restrict__ rhs,
                          const float* __restrict__ cx,
                          const float* __restrict__ cy,
                          float* __restrict__ udst,
                          float* __restrict__ rc, int n, float ih2,
                          int bx0, int by0, int tid, float* pool) {
    float* s1 = pool;
    float* su = pool + 1360;
    const int tx = tid & 31, ty = tid >> 5;

    for (int sp = tid; sp < 20 * 68; sp += 256) {
        int py = sp / 68, px = sp % 68;
        int gy = by0 + py - 2, gx = bx0 + px - 2;
        float v = 0.0f;
        if ((unsigned)gy < (unsigned)n && (unsigned)gx < (unsigned)n) {
            int idx = gy * n + gx;
            float cxe = cx[idx];
            float cxw = (gx > 0) ? cx[idx - 1] : 0.0f;
            float cyn = cy[idx];
            float cys = (gy > 0) ? cy[idx - n] : 0.0f;
            float diag = -((cxe + cxw) + (cyn + cys)) * ih2 - 1.0f;
            v = __fdividef(OMEGA_W * rhs[idx], diag);
        }
        s1[sp] = v;
    }
    __syncthreads();

    for (int sp = tid; sp < 18 * 66; sp += 256) {
        int py = sp / 66, px = sp % 66;
        int gy = by0 + py - 1, gx = bx0 + px - 1;
        float v = 0.0f;
        if ((unsigned)gy < (unsigned)n && (unsigned)gx < (unsigned)n)
            v = jac_sm(s1, py + 1, px + 1, 68, rhs, cx, cy, gy, gx, n, ih2);
        su[sp] = v;
    }
    __syncthreads();

    const int gx0 = bx0 + 2 * tx, gy0 = by0 + 2 * ty;
    const int lx0 = 2 * tx + 1, ly0 = 2 * ty + 1;

    *reinterpret_cast<float2*>(&udst[gy0 * n + gx0]) =
        make_float2(su[ly0 * 66 + lx0], su[ly0 * 66 + lx0 + 1]);
    *reinterpret_cast<float2*>(&udst[(gy0 + 1) * n + gx0]) =
        make_float2(su[(ly0 + 1) * 66 + lx0], su[(ly0 + 1) * 66 + lx0 + 1]);

    float s = resid_sm(su, ly0, lx0, 66, rhs, cx, cy, gy0, gx0, n, ih2) +
              resid_sm(su, ly0, lx0 + 1, 66, rhs, cx, cy, gy0, gx0 + 1, n, ih2) +
              resid_sm(su, ly0 + 1, lx0, 66, rhs, cx, cy, gy0 + 1, gx0, n, ih2) +
              resid_sm(su, ly0 + 1, lx0 + 1, 66, rhs, cx, cy, gy0 + 1, gx0 + 1, n, ih2);
    int nc = n >> 1;
    rc[((by0 >> 1) + ty) * nc + (bx0 >> 1) + tx] = 0.25f * s;
}

__device__ void pjj_tile(const float* __restrict__ u,
                         const float* __restrict__ e,
                         const float* __restrict__ rhs,
                         const float* __restrict__ cx,
                         const float* __restrict__ cy,
                         float* __restrict__ udst, int n, float ih2,
                         int bx0, int by0, int tid, float* pool) {
    float* s1 = pool;
    float* su = pool + 1360;
    const int tx = tid & 31, ty = tid >> 5;
    const int ncc = n >> 1;

    for (int sp = tid; sp < 20 * 68; sp += 256) {
        int py = sp / 68, px = sp % 68;
        int gy = by0 + py - 2, gx = bx0 + px - 2;
        float v = 0.0f;
        if ((unsigned)gy < (unsigned)n && (unsigned)gx < (unsigned)n) {
            int jc = gy >> 1, dj = gy & 1;
            int ic = gx >> 1, di = gx & 1;
            int sj = dj ? 1 : -1;
            int si = di ? 1 : -1;
            bool bi = ((unsigned)(ic + si) < (unsigned)ncc);
            bool bj = ((unsigned)(jc + sj) < (unsigned)ncc);
            float vc = e[jc * ncc + ic];
            float vsi = bi ? e[jc * ncc + ic + si] : 0.0f;
            float vsj = bj ? e[(jc + sj) * ncc + ic] : 0.0f;
            float vd = (bi && bj) ? e[(jc + sj) * ncc + ic + si] : 0.0f;
            float den = 9.0f + 3.0f * (bi ? 1.0f : 0.0f) +
                        3.0f * (bj ? 1.0f : 0.0f) + ((bi && bj) ? 1.0f : 0.0f);
            v = u[gy * n + gx] +
                __fdividef(9.0f * vc + 3.0f * vsi + 3.0f * vsj + vd, den);
        }
        s1[sp] = v;
    }
    __syncthreads();

    for (int sp = tid; sp < 18 * 66; sp += 256) {
        int py = sp / 66, px = sp % 66;
        int gy = by0 + py - 1, gx = bx0 + px - 1;
        float v = 0.0f;
        if ((unsigned)gy < (unsigned)n && (unsigned)gx < (unsigned)n)
            v = jac_sm(s1, py + 1, px + 1, 68, rhs, cx, cy, gy, gx, n, ih2);
        su[sp] = v;
    }
    __syncthreads();

    const int gx0 = bx0 + 2 * tx, gy0 = by0 + 2 * ty;
    const int lx0 = 2 * tx + 1, ly0 = 2 * ty + 1;
    float o00 = jac_sm(su, ly0, lx0, 66, rhs, cx, cy, gy0, gx0, n, ih2);
    float o01 = jac_sm(su, ly0, lx0 + 1, 66, rhs, cx, cy, gy0, gx0 + 1, n, ih2);
    float o10 = jac_sm(su, ly0 + 1, lx0, 66, rhs, cx, cy, gy0 + 1, gx0, n, ih2);
    float o11 = jac_sm(su, ly0 + 1, lx0 + 1, 66, rhs, cx, cy, gy0 + 1, gx0 + 1, n, ih2);
    *reinterpret_cast<float2*>(&udst[gy0 * n + gx0]) = make_float2(o00, o01);
    *reinterpret_cast<float2*>(&udst[(gy0 + 1) * n + gx0]) = make_float2(o10, o11);
}

// ===========================================================================
// Standalone L0 kernels (wide, 2048 CTAs) — thin wrappers over the tiles.
// ===========================================================================
__global__ __launch_bounds__(256)
void jrr0_kernel(const float* __restrict__ rhs,
                 const float* __restrict__ cx,
                 const float* __restrict__ cy,
                 float* __restrict__ udst,
                 float* __restrict__ rc, int n, float ih2) {
    __shared__ float pool[2548];
    jrr0_tile(rhs, cx, cy, udst, rc, n, ih2,
              blockIdx.x * 64, blockIdx.y * 16, threadIdx.x, pool);
}

__global__ __launch_bounds__(256)
void pjj_kernel(const float* __restrict__ u,
                const float* __restrict__ e,
                const float* __restrict__ rhs,
                const float* __restrict__ cx,
                const float* __restrict__ cy,
                float* __restrict__ udst, int n, float ih2) {
    __shared__ float pool[2548];
    pjj_tile(u, e, rhs, cx, cy, udst, n, ih2,
             blockIdx.x * 64, blockIdx.y * 16, threadIdx.x, pool);
}

// jrr2: nonzero-u start (L0 cycle 2 pre-smooth). Kept as R6 (verified).
__global__ __launch_bounds__(256)
void jrr2_kernel(const float* __restrict__ u,
                 const float* __restrict__ rhs,
                 const float* __restrict__ cx,
                 const float* __restrict__ cy,
                 float* __restrict__ udst,
                 float* __restrict__ rc, int n, float ih2) {
    __shared__ float s1[20 * 68];
    __shared__ float su[18 * 66];
    const int tid = threadIdx.x;
    const int tx = tid & 31, ty = tid >> 5;
    const int bx0 = blockIdx.x * 64, by0 = blockIdx.y * 16;

    for (int sp = tid; sp < 20 * 68; sp += 256) {
        int py = sp / 68, px = sp % 68;
        int gy = by0 + py - 2, gx = bx0 + px - 2;
        float v = 0.0f;
        if ((unsigned)gy < (unsigned)n && (unsigned)gx < (unsigned)n)
            v = jac_pt(u, rhs, cx, cy, gy, gx, n, ih2);
        s1[sp] = v;
    }
    __syncthreads();

    for (int sp = tid; sp < 18 * 66; sp += 256) {
        int py = sp / 66, px = sp % 66;
        int gy = by0 + py - 1, gx = bx0 + px - 1;
        float v = 0.0f;
        if ((unsigned)gy < (unsigned)n && (unsigned)gx < (unsigned)n)
            v = jac_sm(s1, py + 1, px + 1, 68, rhs, cx, cy, gy, gx, n, ih2);
        su[sp] = v;
    }
    __syncthreads();

    const int gx0 = bx0 + 2 * tx, gy0 = by0 + 2 * ty;
    const int lx0 = 2 * tx + 1, ly0 = 2 * ty + 1;

    *reinterpret_cast<float2*>(&udst[gy0 * n + gx0]) =
        make_float2(su[ly0 * 66 + lx0], su[ly0 * 66 + lx0 + 1]);
    *reinterpret_cast<float2*>(&udst[(gy0 + 1) * n + gx0]) =
        make_float2(su[(ly0 + 1) * 66 + lx0], su[(ly0 + 1) * 66 + lx0 + 1]);

    float s = resid_sm(su, ly0, lx0, 66, rhs, cx, cy, gy0, gx0, n, ih2) +
              resid_sm(su, ly0, lx0 + 1, 66, rhs, cx, cy, gy0, gx0 + 1, n, ih2) +
              resid_sm(su, ly0 + 1, lx0, 66, rhs, cx, cy, gy0 + 1, gx0, n, ih2) +
              resid_sm(su, ly0 + 1, lx0 + 1, 66, rhs, cx, cy, gy0 + 1, gx0 + 1, n, ih2);
    int nc = n >> 1;
    rc[((by0 >> 1) + ty) * nc + (bx0 >> 1) + tx] = 0.25f * s;
}

// ===========================================================================
// L3 stage inside the middle kernel: 256 CTAs, owned 16x16, halo 11,
// active 38x38 (stride 40). Coeffs (6 pts/thread) in registers; SMEM
// ping-pong; 11 sweeps -> grid barrier (umid exchange) -> 11 sweeps.
// pool must hold >= 3040 floats.
// ===========================================================================
__device__ void l3_stage(const float* __restrict__ r3,
                         const float* __restrict__ cx3,
                         const float* __restrict__ cy3,
                         float* __restrict__ umid,
                         float* __restrict__ uout,
                         int tid, int b, float* pool) {
    float* ua = pool;
    float* ub = pool + 1520;      // 38*40
    const int gx0 = (b & 15) * 16 - 11;
    const int gy0 = (b >> 4) * 16 - 11;
    const float ih2 = 0.015625f;

    int pidx[6];
    float cae[6], caw[6], can[6], cas[6], cb[6], cu[6];
#pragma unroll
    for (int i = 0; i < 6; ++i) {
        int q = tid + 256 * i;
        pidx[i] = -1;
        cae[i] = caw[i] = can[i] = cas[i] = cb[i] = cu[i] = 0.0f;
        if (q < 36 * 36) {
            int py = q / 36 + 1, px = q % 36 + 1;
            pidx[i] = py * 40 + px;
            int gy = gy0 + py, gx = gx0 + px;
            if ((unsigned)gy < (unsigned)N3 && (unsigned)gx < (unsigned)N3) {
                int idx = gy * N3 + gx;
                float cxe = cx3[idx];
                float cxw = (gx > 0) ? cx3[idx - 1] : 0.0f;
                float cyn = cy3[idx];
                float cys = (gy > 0) ? cy3[idx - N3] : 0.0f;
                float wv = __fdividef(OMEGA_W,
                                      -((cxe + cxw) + (cyn + cys)) * ih2 - 1.0f);
                float wi = wv * ih2;
                cae[i] = wi * cxe; caw[i] = wi * cxw;
                can[i] = wi * cyn; cas[i] = wi * cys;
                cb[i] = wv * r3[idx];
            }
        }
    }

    // zero init both buffers (u starts at 0)
    for (int sp = tid; sp < 2 * 1520; sp += 256) pool[sp] = 0.0f;
    __syncthreads();

    float* src = ua;
    float* dst = ub;
#pragma unroll 1
    for (int k = 0; k < 11; ++k) {
#pragma unroll
        for (int i = 0; i < 6; ++i) {
            int p = pidx[i];
            if (p >= 0) {
                float v = (1.0f - OMEGA_W) * cu[i] + cb[i] -
                          (cae[i] * src[p + 1] + caw[i] * src[p - 1] +
                           can[i] * src[p + 40] + cas[i] * src[p - 40]);
                dst[p] = v;
                cu[i] = v;
            }
        }
        __syncthreads();
        float* t = src; src = dst; dst = t;
    }

    // owned 16x16 -> umid; grid barrier; restage with fresh halos
    {
        int py = 11 + (tid >> 4), px = 11 + (tid & 15);
        umid[(gy0 + py) * N3 + (gx0 + px)] = src[py * 40 + px];
    }
    grid_barrier_256();

    for (int sp = tid; sp < 38 * 38; sp += 256) {
        int py = sp / 38, px = sp % 38;
        int p = py * 40 + px;
        int gy = gy0 + py, gx = gx0 + px;
        float v = 0.0f;
        if ((unsigned)gy < (unsigned)N3 && (unsigned)gx < (unsigned)N3)
            v = umid[gy * N3 + gx];
        ua[p] = v; ub[p] = v;
    }
    __syncthreads();
#pragma unroll
    for (int i = 0; i < 6; ++i)
        if (pidx[i] >= 0) cu[i] = ua[pidx[i]];

    src = ua; dst = ub;
#pragma unroll 1
    for (int k = 0; k < 11; ++k) {
#pragma unroll
        for (int i = 0; i < 6; ++i) {
            int p = pidx[i];
            if (p >= 0) {
                float v = (1.0f - OMEGA_W) * cu[i] + cb[i] -
                          (cae[i] * src[p + 1] + caw[i] * src[p - 1] +
                           can[i] * src[p + 40] + cas[i] * src[p - 40]);
                dst[p] = v;
                cu[i] = v;
            }
        }
        __syncthreads();
        float* t = src; src = dst; dst = t;
    }

    {
        int py = 11 + (tid >> 4), px = 11 + (tid & 15);
        uout[(gy0 + py) * N3 + (gx0 + px)] = src[py * 40 + px];
    }
}

// ===========================================================================
// middle_kernel: L1-pre -> L2-pre -> L3 (22 sweeps) -> L2-post -> L1-post
// in ONE persistent launch. 256 CTAs x 256 threads, min 2 CTAs/SM
// (capacity 296 >= 256 ->全 co-resident; grid barriers are deadlock-free).
// ===========================================================================
__global__ __launch_bounds__(256, 2)
void middle_kernel(const float* __restrict__ r1,
                   const float* __restrict__ cx1, const float* __restrict__ cy1,
                   float* __restrict__ u1a, float* __restrict__ r2,
                   const float* __restrict__ cx2, const float* __restrict__ cy2,
                   float* __restrict__ u2a, float* __restrict__ r3,
                   const float* __restrict__ cx3, const float* __restrict__ cy3,
                   float* __restrict__ u3mid, float* __restrict__ u3out,
                   float* __restrict__ u2b, float* __restrict__ u1b) {
    __shared__ float pool[3040];
    const int tid = threadIdx.x;
    const int b = blockIdx.x;

    // Stage A: L1 pre-smooth + resid + restrict (1024 tiles, 4 per CTA)
    for (int t = b; t < 1024; t += 256) {
        int bx0 = (t & 15) * 64, by0 = (t >> 4) * 16;
        jrr0_tile(r1, cx1, cy1, u1a, r2, N1, 0.25f, bx0, by0, tid, pool);
        __syncthreads();
    }
    grid_barrier_256();

    // Stage B: L2 pre-smooth + resid + restrict (256 tiles, 1 per CTA)
    {
        int bx0 = (b & 7) * 64, by0 = (b >> 3) * 16;
        jrr0_tile(r2, cx2, cy2, u2a, r3, N2, 0.0625f, bx0, by0, tid, pool);
        __syncthreads();
    }
    grid_barrier_256();

    // Stage C: L3, all 22 sweeps (internal grid barrier at sweep 11)
    l3_stage(r3, cx3, cy3, u3mid, u3out, tid, b, pool);
    grid_barrier_256();

    // Stage D: L2 correct + post-smooth (1 tile per CTA)
    {
        int bx0 = (b & 7) * 64, by0 = (b >> 3) * 16;
        pjj_tile(u2a, u3out, r2, cx2, cy2, u2b, N2, 0.0625f, bx0, by0, tid, pool);
        __syncthreads();
    }
    grid_barrier_256();

    // Stage E: L1 correct + post-smooth (4 tiles per CTA)
    for (int t = b; t < 1024; t += 256) {
        int bx0 = (t & 15) * 64, by0 = (t >> 4) * 16;
        pjj_tile(u1a, u2b, r1, cx1, cy1, u1b, N1, 0.25f, bx0, by0, tid, pool);
        __syncthreads();
    }
}

// ---------------------------------------------------------------------------
// Host driver: 6 launches total.
// ---------------------------------------------------------------------------
extern "C" void kernel_launch(void* const* d_in, const int* in_sizes, int n_in,
                              void* d_out, int out_size) {
    const float* cx[4];
    const float* cy[4];
    const float* rhs;
    if (in_sizes[2] == in_sizes[0]) {
        for (int l = 0; l < 4; ++l) {
            cx[l] = (const float*)d_in[3 * l + 1];
            cy[l] = (const float*)d_in[3 * l + 2];
        }
        rhs = (const float*)d_in[12];
    } else {
        rhs = (const float*)d_in[0];
        for (int l = 0; l < 4; ++l) {
            cx[l] = (const float*)d_in[5 + l];
            cy[l] = (const float*)d_in[9 + l];
        }
    }

    float* uOUT = (float*)d_out;
    float *uB, *uC;
    float *u1a, *u1b, *r1;
    float *u2a, *u2b, *r2;
    float *u3a, *u3b, *r3;
    cudaGetSymbolAddress((void**)&uB, g_u0b);
    cudaGetSymbolAddress((void**)&uC, g_u0c);
    cudaGetSymbolAddress((void**)&u1a, g_u1a);
    cudaGetSymbolAddress((void**)&u1b, g_u1b);
    cudaGetSymbolAddress((void**)&r1, g_r1);
    cudaGetSymbolAddress((void**)&u2a, g_u2a);
    cudaGetSymbolAddress((void**)&u2b, g_u2b);
    cudaGetSymbolAddress((void**)&r2, g_r2);
    cudaGetSymbolAddress((void**)&u3a, g_u3a);
    cudaGetSymbolAddress((void**)&u3b, g_u3b);
    cudaGetSymbolAddress((void**)&r3, g_r3);

    const float ih2_0 = 1.0f;

    dim3 t0(N0 / 64, N0 / 16);

    for (int cyc = 0; cyc < 2; ++cyc) {
        // ----- level 0: pre-smooth (2) + residual + restrict -> r1; u -> uB
        if (cyc == 0) {
            jrr0_kernel<<<t0, 256>>>(rhs, cx[0], cy[0], uB, r1, N0, ih2_0);
        } else {
            jrr2_kernel<<<t0, 256>>>(uC, rhs, cx[0], cy[0], uB, r1, N0, ih2_0);
        }

        // ----- levels 1..3 + back up to level 1: ONE persistent launch
        middle_kernel<<<256, 256>>>(r1, cx[1], cy[1], u1a, r2,
                                    cx[2], cy[2], u2a, r3,
                                    cx[3], cy[3], u3a, u3b, u2b, u1b);

        // ----- level 0: correct + post (2)
        if (cyc == 0) {
            pjj_kernel<<<t0, 256>>>(uB, u1b, rhs, cx[0], cy[0], uC, N0, ih2_0);
        } else {
            pjj_kernel<<<t0, 256>>>(uB, u1b, rhs, cx[0], cy[0], uOUT, N0, ih2_0);
        }
    }
}

// round 9
// speedup vs baseline: 1.0621x; 1.0621x over previous
#include <cuda_runtime.h>
#include <cstdint>

#define OMEGA_W 0.9f

#define N0 2048
#define N1 1024
#define N2 512
#define N3 256

// Scratch (device globals — no allocation allowed).
__device__ float g_u0b[N0 * N0];
__device__ float g_u0c[N0 * N0];
__device__ float g_u1a[N1 * N1];
__device__ float g_u1b[N1 * N1];
__device__ float g_r1[N1 * N1];
__device__ float g_u2a[N2 * N2];
__device__ float g_u2b[N2 * N2];
__device__ float g_r2[N2 * N2];
__device__ float g_u3a[N3 * N3];
__device__ float g_u3b[N3 * N3];
__device__ float g_r3[N3 * N3];

// Software grid-barrier ticket counter (monotonic; replay-safe under graphs).
__device__ unsigned int g_l3_bar = 0;

// ===========================================================================
// Point helpers — interior (unchecked) and border (checked) variants.
// ===========================================================================
__device__ __forceinline__ float jac_pt_i(const float* __restrict__ u,
                                          const float* __restrict__ rhs,
                                          const float* __restrict__ cx,
                                          const float* __restrict__ cy,
                                          int idx, int n, float ih2) {
    float um = u[idx];
    float cxe = cx[idx], cxw = cx[idx - 1];
    float cyn = cy[idx], cys = cy[idx - n];
    float lap = (cxe * (u[idx + 1] - um) - cxw * (um - u[idx - 1])) * ih2 +
                (cyn * (u[idx + n] - um) - cys * (um - u[idx - n])) * ih2;
    float r = rhs[idx] - (lap - um);
    float diag = -((cxe + cxw) + (cyn + cys)) * ih2 - 1.0f;
    return um + __fdividef(OMEGA_W * r, diag);
}

__device__ __forceinline__ float jac_pt(const float* __restrict__ u,
                                        const float* __restrict__ rhs,
                                        const float* __restrict__ cx,
                                        const float* __restrict__ cy,
                                        int gy, int gx, int n, float ih2) {
    int idx = gy * n + gx;
    float um = u[idx];
    float ue = (gx + 1 < n) ? u[idx + 1] : 0.0f;
    float uw = (gx > 0) ? u[idx - 1] : 0.0f;
    float uN = (gy + 1 < n) ? u[idx + n] : 0.0f;
    float uS = (gy > 0) ? u[idx - n] : 0.0f;
    float cxe = cx[idx];
    float cxw = (gx > 0) ? cx[idx - 1] : 0.0f;
    float cyn = cy[idx];
    float cys = (gy > 0) ? cy[idx - n] : 0.0f;
    float lap = (cxe * (ue - um) - cxw * (um - uw)) * ih2 +
                (cyn * (uN - um) - cys * (um - uS)) * ih2;
    float r = rhs[idx] - (lap - um);
    float diag = -((cxe + cxw) + (cyn + cys)) * ih2 - 1.0f;
    return um + __fdividef(OMEGA_W * r, diag);
}

__device__ __forceinline__ float jac_sm_i(const float* __restrict__ sm,
                                          int lp, int stride,
                                          const float* __restrict__ rhs,
                                          const float* __restrict__ cx,
                                          const float* __restrict__ cy,
                                          int idx, int n, float ih2) {
    float um = sm[lp];
    float cxe = cx[idx], cxw = cx[idx - 1];
    float cyn = cy[idx], cys = cy[idx - n];
    float lap = (cxe * (sm[lp + 1] - um) - cxw * (um - sm[lp - 1])) * ih2 +
                (cyn * (sm[lp + stride] - um) - cys * (um - sm[lp - stride])) * ih2;
    float r = rhs[idx] - (lap - um);
    float diag = -((cxe + cxw) + (cyn + cys)) * ih2 - 1.0f;
    return um + __fdividef(OMEGA_W * r, diag);
}

__device__ __forceinline__ float jac_sm(const float* __restrict__ sm,
                                        int ly, int lx, int stride,
                                        const float* __restrict__ rhs,
                                        const float* __restrict__ cx,
                                        const float* __restrict__ cy,
                                        int gy, int gx, int n, float ih2) {
    int lp = ly * stride + lx;
    float um = sm[lp];
    int idx = gy * n + gx;
    float cxe = cx[idx];
    float cxw = (gx > 0) ? cx[idx - 1] : 0.0f;
    float cyn = cy[idx];
    float cys = (gy > 0) ? cy[idx - n] : 0.0f;
    float lap = (cxe * (sm[lp + 1] - um) - cxw * (um - sm[lp - 1])) * ih2 +
                (cyn * (sm[lp + stride] - um) - cys * (um - sm[lp - stride])) * ih2;
    float r = rhs[idx] - (lap - um);
    float diag = -((cxe + cxw) + (cyn + cys)) * ih2 - 1.0f;
    return um + __fdividef(OMEGA_W * r, diag);
}

__device__ __forceinline__ float resid_sm_i(const float* __restrict__ sm,
                                            int lp, int stride,
                                            const float* __restrict__ rhs,
                                            const float* __restrict__ cx,
                                            const float* __restrict__ cy,
                                            int idx, int n, float ih2) {
    float um = sm[lp];
    float cxe = cx[idx], cxw = cx[idx - 1];
    float cyn = cy[idx], cys = cy[idx - n];
    float lap = (cxe * (sm[lp + 1] - um) - cxw * (um - sm[lp - 1])) * ih2 +
                (cyn * (sm[lp + stride] - um) - cys * (um - sm[lp - stride])) * ih2;
    return rhs[idx] - (lap - um);
}

__device__ __forceinline__ float resid_sm(const float* __restrict__ sm,
                                          int ly, int lx, int stride,
                                          const float* __restrict__ rhs,
                                          const float* __restrict__ cx,
                                          const float* __restrict__ cy,
                                          int gy, int gx, int n, float ih2) {
    int lp = ly * stride + lx;
    float um = sm[lp];
    int idx = gy * n + gx;
    float cxe = cx[idx];
    float cxw = (gx > 0) ? cx[idx - 1] : 0.0f;
    float cyn = cy[idx];
    float cys = (gy > 0) ? cy[idx - n] : 0.0f;
    float lap = (cxe * (sm[lp + 1] - um) - cxw * (um - sm[lp - 1])) * ih2 +
                (cyn * (sm[lp + stride] - um) - cys * (um - sm[lp - stride])) * ih2;
    return rhs[idx] - (lap - um);
}

// ===========================================================================
// Shared phase-2/3 tail: jacobi s1(20x68)->su(18x66), then store u + resid +
// restrict. Used by jrr0/jrr2 after their phase-1 fills s1.
// ===========================================================================
template <bool IN>
__device__ __forceinline__ void jrr_tail(float* __restrict__ s1,
                                         float* __restrict__ su,
                                         const float* __restrict__ rhs,
                                         const float* __restrict__ cx,
                                         const float* __restrict__ cy,
                                         float* __restrict__ udst,
                                         float* __restrict__ rc,
                                         int n, float ih2,
                                         int bx0, int by0, int lane, int wid) {
    // phase 2: su[py*66+px] = jacobi of point (y=py-1, x=px-1)
    for (int py = wid; py < 18; py += 8) {
        int gy = by0 + py - 1;
        int grow = gy * n + bx0 - 1;
        float* drow = su + py * 66;
        if (IN) {
            for (int px = lane; px < 66; px += 32)
                drow[px] = jac_sm_i(s1, (py + 1) * 68 + px + 1, 68,
                                    rhs, cx, cy, grow + px, n, ih2);
        } else {
            bool rok = (unsigned)gy < (unsigned)n;
            for (int px = lane; px < 66; px += 32) {
                int gx = bx0 + px - 1;
                float v = 0.0f;
                if (rok && (unsigned)gx < (unsigned)n)
                    v = jac_sm(s1, py + 1, px + 1, 68, rhs, cx, cy, gy, gx, n, ih2);
                drow[px] = v;
            }
        }
    }
    __syncthreads();

    // phase 3: store owned 2x2 + residual + restrict
    const int tx = lane, ty = wid;
    const int gx0 = bx0 + 2 * tx, gy0 = by0 + 2 * ty;
    const int lx0 = 2 * tx + 1, ly0 = 2 * ty + 1;

    *reinterpret_cast<float2*>(&udst[gy0 * n + gx0]) =
        make_float2(su[ly0 * 66 + lx0], su[ly0 * 66 + lx0 + 1]);
    *reinterpret_cast<float2*>(&udst[(gy0 + 1) * n + gx0]) =
        make_float2(su[(ly0 + 1) * 66 + lx0], su[(ly0 + 1) * 66 + lx0 + 1]);

    float s;
    if (IN) {
        int i00 = gy0 * n + gx0;
        s = resid_sm_i(su, ly0 * 66 + lx0, 66, rhs, cx, cy, i00, n, ih2) +
            resid_sm_i(su, ly0 * 66 + lx0 + 1, 66, rhs, cx, cy, i00 + 1, n, ih2) +
            resid_sm_i(su, (ly0 + 1) * 66 + lx0, 66, rhs, cx, cy, i00 + n, n, ih2) +
            resid_sm_i(su, (ly0 + 1) * 66 + lx0 + 1, 66, rhs, cx, cy, i00 + n + 1, n, ih2);
    } else {
        s = resid_sm(su, ly0, lx0, 66, rhs, cx, cy, gy0, gx0, n, ih2) +
            resid_sm(su, ly0, lx0 + 1, 66, rhs, cx, cy, gy0, gx0 + 1, n, ih2) +
            resid_sm(su, ly0 + 1, lx0, 66, rhs, cx, cy, gy0 + 1, gx0, n, ih2) +
            resid_sm(su, ly0 + 1, lx0 + 1, 66, rhs, cx, cy, gy0 + 1, gx0 + 1, n, ih2);
    }
    int nc = n >> 1;
    rc[((by0 >> 1) + ty) * nc + (bx0 >> 1) + tx] = 0.25f * s;
}

// ===========================================================================
// jrr0: u==0 start. sweep1 (local) -> sweep2 -> residual -> restrict.
// ===========================================================================
template <bool IN>
__device__ __forceinline__ void jrr0_tile(const float* __restrict__ rhs,
                                          const float* __restrict__ cx,
                                          const float* __restrict__ cy,
                                          float* __restrict__ udst,
                                          float* __restrict__ rc,
                                          int n, float ih2,
                                          int bx0, int by0, int tid,
                                          float* s1, float* su) {
    const int lane = tid & 31, wid = tid >> 5;
    // phase 1: s1[py*68+px] = omega*rhs/diag at (y=py-2, x=px-2)
    for (int py = wid; py < 20; py += 8) {
        int gy = by0 + py - 2;
        int grow = gy * n + bx0 - 2;
        float* srow = s1 + py * 68;
        if (IN) {
            for (int px = lane; px < 68; px += 32) {
                int idx = grow + px;
                float cxe = cx[idx], cxw = cx[idx - 1];
                float cyn = cy[idx], cys = cy[idx - n];
                float diag = -((cxe + cxw) + (cyn + cys)) * ih2 - 1.0f;
                srow[px] = __fdividef(OMEGA_W * rhs[idx], diag);
            }
        } else {
            bool rok = (unsigned)gy < (unsigned)n;
            for (int px = lane; px < 68; px += 32) {
                int gx = bx0 + px - 2;
                float v = 0.0f;
                if (rok && (unsigned)gx < (unsigned)n) {
                    int idx = grow + px;
                    float cxe = cx[idx];
                    float cxw = (gx > 0) ? cx[idx - 1] : 0.0f;
                    float cyn = cy[idx];
                    float cys = (gy > 0) ? cy[idx - n] : 0.0f;
                    float diag = -((cxe + cxw) + (cyn + cys)) * ih2 - 1.0f;
                    v = __fdividef(OMEGA_W * rhs[idx], diag);
                }
                srow[px] = v;
            }
        }
    }
    __syncthreads();
    jrr_tail<IN>(s1, su, rhs, cx, cy, udst, rc, n, ih2, bx0, by0, lane, wid);
}

__global__ __launch_bounds__(256)
void jrr0_kernel(const float* __restrict__ rhs,
                 const float* __restrict__ cx,
                 const float* __restrict__ cy,
                 float* __restrict__ udst,
                 float* __restrict__ rc, int n, float ih2) {
    __shared__ float s1[20 * 68];
    __shared__ float su[18 * 66];
    int bx0 = blockIdx.x * 64, by0 = blockIdx.y * 16;
    bool in = blockIdx.x > 0 && blockIdx.y > 0 &&
              blockIdx.x < gridDim.x - 1 && blockIdx.y < gridDim.y - 1;
    if (in)
        jrr0_tile<true>(rhs, cx, cy, udst, rc, n, ih2, bx0, by0, threadIdx.x, s1, su);
    else
        jrr0_tile<false>(rhs, cx, cy, udst, rc, n, ih2, bx0, by0, threadIdx.x, s1, su);
}

// ===========================================================================
// jrr2: nonzero u start (phase 1 reads global u with halo 2).
// ===========================================================================
template <bool IN>
__device__ __forceinline__ void jrr2_tile(const float* __restrict__ u,
                                          const float* __restrict__ rhs,
                                          const float* __restrict__ cx,
                                          const float* __restrict__ cy,
                                          float* __restrict__ udst,
                                          float* __restrict__ rc,
                                          int n, float ih2,
                                          int bx0, int by0, int tid,
                                          float* s1, float* su) {
    const int lane = tid & 31, wid = tid >> 5;
    for (int py = wid; py < 20; py += 8) {
        int gy = by0 + py - 2;
        int grow = gy * n + bx0 - 2;
        float* srow = s1 + py * 68;
        if (IN) {
            for (int px = lane; px < 68; px += 32)
                srow[px] = jac_pt_i(u, rhs, cx, cy, grow + px, n, ih2);
        } else {
            bool rok = (unsigned)gy < (unsigned)n;
            for (int px = lane; px < 68; px += 32) {
                int gx = bx0 + px - 2;
                float v = 0.0f;
                if (rok && (unsigned)gx < (unsigned)n)
                    v = jac_pt(u, rhs, cx, cy, gy, gx, n, ih2);
                srow[px] = v;
            }
        }
    }
    __syncthreads();
    jrr_tail<IN>(s1, su, rhs, cx, cy, udst, rc, n, ih2, bx0, by0, lane, wid);
}

__global__ __launch_bounds__(256)
void jrr2_kernel(const float* __restrict__ u,
                 const float* __restrict__ rhs,
                 const float* __restrict__ cx,
                 const float* __restrict__ cy,
                 float* __restrict__ udst,
                 float* __restrict__ rc, int n, float ih2) {
    __shared__ float s1[20 * 68];
    __shared__ float su[18 * 66];
    int bx0 = blockIdx.x * 64, by0 = blockIdx.y * 16;
    bool in = blockIdx.x > 0 && blockIdx.y > 0 &&
              blockIdx.x < gridDim.x - 1 && blockIdx.y < gridDim.y - 1;
    if (in)
        jrr2_tile<true>(u, rhs, cx, cy, udst, rc, n, ih2, bx0, by0, threadIdx.x, s1, su);
    else
        jrr2_tile<false>(u, rhs, cx, cy, udst, rc, n, ih2, bx0, by0, threadIdx.x, s1, su);
}

// ===========================================================================
// pjj: {u += prolong(e)} + two Jacobi sweeps.
// ===========================================================================
template <bool IN>
__device__ __forceinline__ void pjj_tile(const float* __restrict__ u,
                                         const float* __restrict__ e,
                                         const float* __restrict__ rhs,
                                         const float* __restrict__ cx,
                                         const float* __restrict__ cy,
                                         float* __restrict__ udst,
                                         int n, float ih2,
                                         int bx0, int by0, int tid,
                                         float* s1, float* su) {
    const int lane = tid & 31, wid = tid >> 5;
    const int ncc = n >> 1;

    // phase 0: prolong-corrected u -> s1 (20x68, origin -2,-2)
    for (int py = wid; py < 20; py += 8) {
        int gy = by0 + py - 2;
        int grow = gy * n + bx0 - 2;
        float* srow = s1 + py * 68;
        int jc = gy >> 1;
        int sj = (gy & 1) ? 1 : -1;
        if (IN) {
            const float* er = e + jc * ncc;
            const float* erj = e + (jc + sj) * ncc;
            for (int px = lane; px < 68; px += 32) {
                int gx = bx0 + px - 2;
                int ic = gx >> 1;
                int si = (gx & 1) ? 1 : -1;
                float w = 9.0f * er[ic] + 3.0f * er[ic + si] +
                          3.0f * erj[ic] + erj[ic + si];
                srow[px] = u[grow + px] + w * 0.0625f;
            }
        } else {
            bool rok = (unsigned)gy < (unsigned)n;
            bool bj = ((unsigned)(jc + sj) < (unsigned)ncc);
            for (int px = lane; px < 68; px += 32) {
                int gx = bx0 + px - 2;
                float v = 0.0f;
                if (rok && (unsigned)gx < (unsigned)n) {
                    int ic = gx >> 1;
                    int si = (gx & 1) ? 1 : -1;
                    bool bi = ((unsigned)(ic + si) < (unsigned)ncc);
                    float vc = e[jc * ncc + ic];
                    float vsi = bi ? e[jc * ncc + ic + si] : 0.0f;
                    float vsj = bj ? e[(jc + sj) * ncc + ic] : 0.0f;
                    float vd = (bi && bj) ? e[(jc + sj) * ncc + ic + si] : 0.0f;
                    float den = 9.0f + 3.0f * (bi ? 1.0f : 0.0f) +
                                3.0f * (bj ? 1.0f : 0.0f) + ((bi && bj) ? 1.0f : 0.0f);
                    v = u[grow + px] +
                        __fdividef(9.0f * vc + 3.0f * vsi + 3.0f * vsj + vd, den);
                }
                srow[px] = v;
            }
        }
    }
    __syncthreads();

    // phase 1: jacobi s1 -> su (18x66)
    for (int py = wid; py < 18; py += 8) {
        int gy = by0 + py - 1;
        int grow = gy * n + bx0 - 1;
        float* drow = su + py * 66;
        if (IN) {
            for (int px = lane; px < 66; px += 32)
                drow[px] = jac_sm_i(s1, (py + 1) * 68 + px + 1, 68,
                                    rhs, cx, cy, grow + px, n, ih2);
        } else {
            bool rok = (unsigned)gy < (unsigned)n;
            for (int px = lane; px < 66; px += 32) {
                int gx = bx0 + px - 1;
                float v = 0.0f;
                if (rok && (unsigned)gx < (unsigned)n)
                    v = jac_sm(s1, py + 1, px + 1, 68, rhs, cx, cy, gy, gx, n, ih2);
                drow[px] = v;
            }
        }
    }
    __syncthreads();

    // phase 2: jacobi at owned 2x2 + store
    const int tx = lane, ty = wid;
    const int gx0 = bx0 + 2 * tx, gy0 = by0 + 2 * ty;
    const int lx0 = 2 * tx + 1, ly0 = 2 * ty + 1;
    float o00, o01, o10, o11;
    if (IN) {
        int i00 = gy0 * n + gx0;
        o00 = jac_sm_i(su, ly0 * 66 + lx0, 66, rhs, cx, cy, i00, n, ih2);
        o01 = jac_sm_i(su, ly0 * 66 + lx0 + 1, 66, rhs, cx, cy, i00 + 1, n, ih2);
        o10 = jac_sm_i(su, (ly0 + 1) * 66 + lx0, 66, rhs, cx, cy, i00 + n, n, ih2);
        o11 = jac_sm_i(su, (ly0 + 1) * 66 + lx0 + 1, 66, rhs, cx, cy, i00 + n + 1, n, ih2);
    } else {
        o00 = jac_sm(su, ly0, lx0, 66, rhs, cx, cy, gy0, gx0, n, ih2);
        o01 = jac_sm(su, ly0, lx0 + 1, 66, rhs, cx, cy, gy0, gx0 + 1, n, ih2);
        o10 = jac_sm(su, ly0 + 1, lx0, 66, rhs, cx, cy, gy0 + 1, gx0, n, ih2);
        o11 = jac_sm(su, ly0 + 1, lx0 + 1, 66, rhs, cx, cy, gy0 + 1, gx0 + 1, n, ih2);
    }
    *reinterpret_cast<float2*>(&udst[gy0 * n + gx0]) = make_float2(o00, o01);
    *reinterpret_cast<float2*>(&udst[(gy0 + 1) * n + gx0]) = make_float2(o10, o11);
}

__global__ __launch_bounds__(256)
void pjj_kernel(const float* __restrict__ u,
                const float* __restrict__ e,
                const float* __restrict__ rhs,
                const float* __restrict__ cx,
                const float* __restrict__ cy,
                float* __restrict__ udst, int n, float ih2) {
    __shared__ float s1[20 * 68];
    __shared__ float su[18 * 66];
    int bx0 = blockIdx.x * 64, by0 = blockIdx.y * 16;
    bool in = blockIdx.x > 0 && blockIdx.y > 0 &&
              blockIdx.x < gridDim.x - 1 && blockIdx.y < gridDim.y - 1;
    if (in)
        pjj_tile<true>(u, e, rhs, cx, cy, udst, n, ih2, bx0, by0, threadIdx.x, s1, su);
    else
        pjj_tile<false>(u, e, rhs, cx, cy, udst, n, ih2, bx0, by0, threadIdx.x, s1, su);
}

// ===========================================================================
// l3_one (R7, measured 15.2us): all 22 coarsest sweeps in one launch.
// 128 CTAs (8x16), 512 threads, owned 32x16, halo 11; coeffs in registers;
// SMEM ping-pong; software grid barrier at sweep 11.
// ===========================================================================
#define L3S 56

__global__ __launch_bounds__(512)
void l3_one_kernel(const float* __restrict__ r3,
                   const float* __restrict__ cx3,
                   const float* __restrict__ cy3,
                   float* __restrict__ umid,
                   float* __restrict__ uout) {
    __shared__ float ua[38 * L3S], ub[38 * L3S];
    const int tid = threadIdx.x;
    const int gx0 = blockIdx.x * 32 - 11;
    const int gy0 = blockIdx.y * 16 - 11;
    const float ih2 = 0.015625f;

    int pidx[4];
    float cae[4], caw[4], can[4], cas[4], cb[4], cu[4];
#pragma unroll
    for (int i = 0; i < 4; ++i) {
        int q = tid + 512 * i;
        pidx[i] = -1;
        cae[i] = caw[i] = can[i] = cas[i] = cb[i] = cu[i] = 0.0f;
        if (q < 36 * 52) {
            int py = q / 52 + 1, px = q % 52 + 1;
            pidx[i] = py * L3S + px;
            int gy = gy0 + py, gx = gx0 + px;
            if ((unsigned)gy < (unsigned)N3 && (unsigned)gx < (unsigned)N3) {
                int idx = gy * N3 + gx;
                float cxe = cx3[idx];
                float cxw = (gx > 0) ? cx3[idx - 1] : 0.0f;
                float cyn = cy3[idx];
                float cys = (gy > 0) ? cy3[idx - N3] : 0.0f;
                float wv = __fdividef(OMEGA_W,
                                      -((cxe + cxw) + (cyn + cys)) * ih2 - 1.0f);
                float wi = wv * ih2;
                cae[i] = wi * cxe; caw[i] = wi * cxw;
                can[i] = wi * cyn; cas[i] = wi * cys;
                cb[i] = wv * r3[idx];
            }
        }
    }

    for (int sp = tid; sp < 38 * L3S; sp += 512) { ua[sp] = 0.0f; ub[sp] = 0.0f; }
    __syncthreads();

    float* src = ua;
    float* dst = ub;
#pragma unroll 1
    for (int k = 0; k < 11; ++k) {
#pragma unroll
        for (int i = 0; i < 4; ++i) {
            int p = pidx[i];
            if (p >= 0) {
                float v = (1.0f - OMEGA_W) * cu[i] + cb[i] -
                          (cae[i] * src[p + 1] + caw[i] * src[p - 1] +
                           can[i] * src[p + L3S] + cas[i] * src[p - L3S]);
                dst[p] = v;
                cu[i] = v;
            }
        }
        __syncthreads();
        float* t = src; src = dst; dst = t;
    }

    {
        int py = 11 + (tid >> 5), px = 11 + (tid & 31);
        umid[(gy0 + py) * N3 + (gx0 + px)] = src[py * L3S + px];
    }
    __threadfence();
    __syncthreads();
    if (tid == 0) {
        unsigned ticket = atomicAdd(&g_l3_bar, 1u);
        unsigned target = (ticket / 128u + 1u) * 128u;
        while (*(volatile unsigned*)&g_l3_bar < target) __nanosleep(128);
    }
    __syncthreads();

    for (int sp = tid; sp < 38 * 54; sp += 512) {
        int py = sp / 54, px = sp % 54;
        int p = py * L3S + px;
        int gy = gy0 + py, gx = gx0 + px;
        float v = 0.0f;
        if ((unsigned)gy < (unsigned)N3 && (unsigned)gx < (unsigned)N3)
            v = umid[gy * N3 + gx];
        ua[p] = v; ub[p] = v;
    }
    __syncthreads();
#pragma unroll
    for (int i = 0; i < 4; ++i)
        if (pidx[i] >= 0) cu[i] = ua[pidx[i]];

    src = ua; dst = ub;
#pragma unroll 1
    for (int k = 0; k < 11; ++k) {
#pragma unroll
        for (int i = 0; i < 4; ++i) {
            int p = pidx[i];
            if (p >= 0) {
                float v = (1.0f - OMEGA_W) * cu[i] + cb[i] -
                          (cae[i] * src[p + 1] + caw[i] * src[p - 1] +
                           can[i] * src[p + L3S] + cas[i] * src[p - L3S]);
                dst[p] = v;
                cu[i] = v;
            }
        }
        __syncthreads();
        float* t = src; src = dst; dst = t;
    }

    {
        int py = 11 + (tid >> 5), px = 11 + (tid & 31);
        uout[(gy0 + py) * N3 + (gx0 + px)] = src[py * L3S + px];
    }
}

// ---------------------------------------------------------------------------
// Host driver (R6 structure + l3_one): 14 launches.
// ---------------------------------------------------------------------------
extern "C" void kernel_launch(void* const* d_in, const int* in_sizes, int n_in,
                              void* d_out, int out_size) {
    const float* cx[4];
    const float* cy[4];
    const float* rhs;
    if (in_sizes[2] == in_sizes[0]) {
        for (int l = 0; l < 4; ++l) {
            cx[l] = (const float*)d_in[3 * l + 1];
            cy[l] = (const float*)d_in[3 * l + 2];
        }
        rhs = (const float*)d_in[12];
    } else {
        rhs = (const float*)d_in[0];
        for (int l = 0; l < 4; ++l) {
            cx[l] = (const float*)d_in[5 + l];
            cy[l] = (const float*)d_in[9 + l];
        }
    }

    float* uOUT = (float*)d_out;
    float *uB, *uC;
    float *u1a, *u1b, *r1;
    float *u2a, *u2b, *r2;
    float *u3a, *u3b, *r3;
    cudaGetSymbolAddress((void**)&uB, g_u0b);
    cudaGetSymbolAddress((void**)&uC, g_u0c);
    cudaGetSymbolAddress((void**)&u1a, g_u1a);
    cudaGetSymbolAddress((void**)&u1b, g_u1b);
    cudaGetSymbolAddress((void**)&r1, g_r1);
    cudaGetSymbolAddress((void**)&u2a, g_u2a);
    cudaGetSymbolAddress((void**)&u2b, g_u2b);
    cudaGetSymbolAddress((void**)&r2, g_r2);
    cudaGetSymbolAddress((void**)&u3a, g_u3a);
    cudaGetSymbolAddress((void**)&u3b, g_u3b);
    cudaGetSymbolAddress((void**)&r3, g_r3);

    const float ih2_0 = 1.0f, ih2_1 = 0.25f, ih2_2 = 0.0625f;

    dim3 t0(N0 / 64, N0 / 16);
    dim3 t1(N1 / 64, N1 / 16);
    dim3 t2(N2 / 64, N2 / 16);
    dim3 g3(8, 16);

    for (int cyc = 0; cyc < 2; ++cyc) {
        // ----- level 0: pre-smooth (2) + residual + restrict -> r1; u -> uB
        if (cyc == 0) {
            jrr0_kernel<<<t0, 256>>>(rhs, cx[0], cy[0], uB, r1, N0, ih2_0);
        } else {
            jrr2_kernel<<<t0, 256>>>(uC, rhs, cx[0], cy[0], uB, r1, N0, ih2_0);
        }

        // ----- level 1: pre (from zero) + residual + restrict -> r2
        jrr0_kernel<<<t1, 256>>>(r1, cx[1], cy[1], u1a, r2, N1, ih2_1);

        // ----- level 2: pre (from zero) + residual + restrict -> r3
        jrr0_kernel<<<t2, 256>>>(r2, cx[2], cy[2], u2a, r3, N2, ih2_2);

        // ----- level 3: all 22 sweeps in one launch
        l3_one_kernel<<<g3, 512>>>(r3, cx[3], cy[3], u3a, u3b);

        // ----- level 2: correct + post (2) -> u2b
        pjj_kernel<<<t2, 256>>>(u2a, u3b, r2, cx[2], cy[2], u2b, N2, ih2_2);

        // ----- level 1: correct + post (2) -> u1b
        pjj_kernel<<<t1, 256>>>(u1a, u2b, r1, cx[1], cy[1], u1b, N1, ih2_1);

        // ----- level 0: correct + post (2)
        if (cyc == 0) {
            pjj_kernel<<<t0, 256>>>(uB, u1b, rhs, cx[0], cy[0], uC, N0, ih2_0);
        } else {
            pjj_kernel<<<t0, 256>>>(uB, u1b, rhs, cx[0], cy[0], uOUT, N0, ih2_0);
        }
    }
}

// round 10
// speedup vs baseline: 1.2192x; 1.1480x over previous
#include <cuda_runtime.h>
#include <cstdint>

#define OMEGA_W 0.9f

#define N0 2048
#define N1 1024
#define N2 512
#define N3 256

// Scratch (device globals — no allocation allowed).
__device__ float g_u0b[N0 * N0];
__device__ float g_u0c[N0 * N0];
__device__ float g_u1a[N1 * N1];
__device__ float g_u1b[N1 * N1];
__device__ float g_r1[N1 * N1];
__device__ float g_u2a[N2 * N2];
__device__ float g_u2b[N2 * N2];
__device__ float g_r2[N2 * N2];
__device__ float g_u3a[N3 * N3];
__device__ float g_u3b[N3 * N3];
__device__ float g_r3[N3 * N3];

// Software grid-barrier ticket counter (monotonic; replay-safe under graphs).
__device__ unsigned int g_bar = 0;

__device__ __forceinline__ void grid_barrier_256() {
    __syncthreads();
    __threadfence();
    if (threadIdx.x == 0) {
        unsigned ticket = atomicAdd(&g_bar, 1u);
        unsigned target = (ticket / 256u + 1u) * 256u;
        while (*(volatile unsigned*)&g_bar < target) __nanosleep(64);
    }
    __syncthreads();
    __threadfence();
}

// ---------------------------------------------------------------------------
// Point helpers (R6 versions — verified at 242.2us).
// ---------------------------------------------------------------------------
__device__ __forceinline__ float jac_pt(const float* __restrict__ u,
                                        const float* __restrict__ rhs,
                                        const float* __restrict__ cx,
                                        const float* __restrict__ cy,
                                        int gy, int gx, int n, float ih2) {
    int idx = gy * n + gx;
    float um = u[idx];
    float ue = (gx + 1 < n) ? u[idx + 1] : 0.0f;
    float uw = (gx > 0) ? u[idx - 1] : 0.0f;
    float uN = (gy + 1 < n) ? u[idx + n] : 0.0f;
    float uS = (gy > 0) ? u[idx - n] : 0.0f;
    float cxe = cx[idx];
    float cxw = (gx > 0) ? cx[idx - 1] : 0.0f;
    float cyn = cy[idx];
    float cys = (gy > 0) ? cy[idx - n] : 0.0f;
    float lap = (cxe * (ue - um) - cxw * (um - uw)) * ih2 +
                (cyn * (uN - um) - cys * (um - uS)) * ih2;
    float r = rhs[idx] - (lap - um);
    float diag = -((cxe + cxw) + (cyn + cys)) * ih2 - 1.0f;
    return um + __fdividef(OMEGA_W * r, diag);
}

__device__ __forceinline__ float jac_sm(const float* __restrict__ sm,
                                        int ly, int lx, int stride,
                                        const float* __restrict__ rhs,
                                        const float* __restrict__ cx,
                                        const float* __restrict__ cy,
                                        int gy, int gx, int n, float ih2) {
    int lp = ly * stride + lx;
    float um = sm[lp];
    int idx = gy * n + gx;
    float cxe = cx[idx];
    float cxw = (gx > 0) ? cx[idx - 1] : 0.0f;
    float cyn = cy[idx];
    float cys = (gy > 0) ? cy[idx - n] : 0.0f;
    float lap = (cxe * (sm[lp + 1] - um) - cxw * (um - sm[lp - 1])) * ih2 +
                (cyn * (sm[lp + stride] - um) - cys * (um - sm[lp - stride])) * ih2;
    float r = rhs[idx] - (lap - um);
    float diag = -((cxe + cxw) + (cyn + cys)) * ih2 - 1.0f;
    return um + __fdividef(OMEGA_W * r, diag);
}

__device__ __forceinline__ float resid_sm(const float* __restrict__ sm,
                                          int ly, int lx, int stride,
                                          const float* __restrict__ rhs,
                                          const float* __restrict__ cx,
                                          const float* __restrict__ cy,
                                          int gy, int gx, int n, float ih2) {
    int lp = ly * stride + lx;
    float um = sm[lp];
    int idx = gy * n + gx;
    float cxe = cx[idx];
    float cxw = (gx > 0) ? cx[idx - 1] : 0.0f;
    float cyn = cy[idx];
    float cys = (gy > 0) ? cy[idx - n] : 0.0f;
    float lap = (cxe * (sm[lp + 1] - um) - cxw * (um - sm[lp - 1])) * ih2 +
                (cyn * (sm[lp + stride] - um) - cys * (um - sm[lp - stride])) * ih2;
    return rhs[idx] - (lap - um);
}

// ===========================================================================
// Tile bodies (R6 flat-sp-loop versions, as device functions).
// pool >= 2548 floats: s1 = pool[0..1360), su = pool[1360..2548).
// ===========================================================================
__device__ void jrr0_tile(const float* __restrict__ rhs,
                          const float* __restrict__ cx,
                          const float* __restrict__ cy,
                          float* __restrict__ udst,
                          float* __restrict__ rc, int n, float ih2,
                          int bx0, int by0, int tid, float* pool) {
    float* s1 = pool;
    float* su = pool + 1360;
    const int tx = tid & 31, ty = tid >> 5;

    for (int sp = tid; sp < 20 * 68; sp += 256) {
        int py = sp / 68, px = sp % 68;
        int gy = by0 + py - 2, gx = bx0 + px - 2;
        float v = 0.0f;
        if ((unsigned)gy < (unsigned)n && (unsigned)gx < (unsigned)n) {
            int idx = gy * n + gx;
            float cxe = cx[idx];
            float cxw = (gx > 0) ? cx[idx - 1] : 0.0f;
            float cyn = cy[idx];
            float cys = (gy > 0) ? cy[idx - n] : 0.0f;
            float diag = -((cxe + cxw) + (cyn + cys)) * ih2 - 1.0f;
            v = __fdividef(OMEGA_W * rhs[idx], diag);
        }
        s1[sp] = v;
    }
    __syncthreads();

    for (int sp = tid; sp < 18 * 66; sp += 256) {
        int py = sp / 66, px = sp % 66;
        int gy = by0 + py - 1, gx = bx0 + px - 1;
        float v = 0.0f;
        if ((unsigned)gy < (unsigned)n && (unsigned)gx < (unsigned)n)
            v = jac_sm(s1, py + 1, px + 1, 68, rhs, cx, cy, gy, gx, n, ih2);
        su[sp] = v;
    }
    __syncthreads();

    const int gx0 = bx0 + 2 * tx, gy0 = by0 + 2 * ty;
    const int lx0 = 2 * tx + 1, ly0 = 2 * ty + 1;

    *reinterpret_cast<float2*>(&udst[gy0 * n + gx0]) =
        make_float2(su[ly0 * 66 + lx0], su[ly0 * 66 + lx0 + 1]);
    *reinterpret_cast<float2*>(&udst[(gy0 + 1) * n + gx0]) =
        make_float2(su[(ly0 + 1) * 66 + lx0], su[(ly0 + 1) * 66 + lx0 + 1]);

    float s = resid_sm(su, ly0, lx0, 66, rhs, cx, cy, gy0, gx0, n, ih2) +
              resid_sm(su, ly0, lx0 + 1, 66, rhs, cx, cy, gy0, gx0 + 1, n, ih2) +
              resid_sm(su, ly0 + 1, lx0, 66, rhs, cx, cy, gy0 + 1, gx0, n, ih2) +
              resid_sm(su, ly0 + 1, lx0 + 1, 66, rhs, cx, cy, gy0 + 1, gx0 + 1, n, ih2);
    int nc = n >> 1;
    rc[((by0 >> 1) + ty) * nc + (bx0 >> 1) + tx] = 0.25f * s;
}

__device__ void pjj_tile(const float* __restrict__ u,
                         const float* __restrict__ e,
                         const float* __restrict__ rhs,
                         const float* __restrict__ cx,
                         const float* __restrict__ cy,
                         float* __restrict__ udst, int n, float ih2,
                         int bx0, int by0, int tid, float* pool) {
    float* s1 = pool;
    float* su = pool + 1360;
    const int tx = tid & 31, ty = tid >> 5;
    const int ncc = n >> 1;

    for (int sp = tid; sp < 20 * 68; sp += 256) {
        int py = sp / 68, px = sp % 68;
        int gy = by0 + py - 2, gx = bx0 + px - 2;
        float v = 0.0f;
        if ((unsigned)gy < (unsigned)n && (unsigned)gx < (unsigned)n) {
            int jc = gy >> 1, dj = gy & 1;
            int ic = gx >> 1, di = gx & 1;
            int sj = dj ? 1 : -1;
            int si = di ? 1 : -1;
            bool bi = ((unsigned)(ic + si) < (unsigned)ncc);
            bool bj = ((unsigned)(jc + sj) < (unsigned)ncc);
            float vc = e[jc * ncc + ic];
            float vsi = bi ? e[jc * ncc + ic + si] : 0.0f;
            float vsj = bj ? e[(jc + sj) * ncc + ic] : 0.0f;
            float vd = (bi && bj) ? e[(jc + sj) * ncc + ic + si] : 0.0f;
            float den = 9.0f + 3.0f * (bi ? 1.0f : 0.0f) +
                        3.0f * (bj ? 1.0f : 0.0f) + ((bi && bj) ? 1.0f : 0.0f);
            v = u[gy * n + gx] +
                __fdividef(9.0f * vc + 3.0f * vsi + 3.0f * vsj + vd, den);
        }
        s1[sp] = v;
    }
    __syncthreads();

    for (int sp = tid; sp < 18 * 66; sp += 256) {
        int py = sp / 66, px = sp % 66;
        int gy = by0 + py - 1, gx = bx0 + px - 1;
        float v = 0.0f;
        if ((unsigned)gy < (unsigned)n && (unsigned)gx < (unsigned)n)
            v = jac_sm(s1, py + 1, px + 1, 68, rhs, cx, cy, gy, gx, n, ih2);
        su[sp] = v;
    }
    __syncthreads();

    const int gx0 = bx0 + 2 * tx, gy0 = by0 + 2 * ty;
    const int lx0 = 2 * tx + 1, ly0 = 2 * ty + 1;
    float o00 = jac_sm(su, ly0, lx0, 66, rhs, cx, cy, gy0, gx0, n, ih2);
    float o01 = jac_sm(su, ly0, lx0 + 1, 66, rhs, cx, cy, gy0, gx0 + 1, n, ih2);
    float o10 = jac_sm(su, ly0 + 1, lx0, 66, rhs, cx, cy, gy0 + 1, gx0, n, ih2);
    float o11 = jac_sm(su, ly0 + 1, lx0 + 1, 66, rhs, cx, cy, gy0 + 1, gx0 + 1, n, ih2);
    *reinterpret_cast<float2*>(&udst[gy0 * n + gx0]) = make_float2(o00, o01);
    *reinterpret_cast<float2*>(&udst[(gy0 + 1) * n + gx0]) = make_float2(o10, o11);
}

// ===========================================================================
// Standalone wide kernels (L0/L1) — thin wrappers, R6 shapes.
// ===========================================================================
__global__ __launch_bounds__(256)
void jrr0_kernel(const float* __restrict__ rhs,
                 const float* __restrict__ cx,
                 const float* __restrict__ cy,
                 float* __restrict__ udst,
                 float* __restrict__ rc, int n, float ih2) {
    __shared__ float pool[2548];
    jrr0_tile(rhs, cx, cy, udst, rc, n, ih2,
              blockIdx.x * 64, blockIdx.y * 16, threadIdx.x, pool);
}

__global__ __launch_bounds__(256)
void pjj_kernel(const float* __restrict__ u,
                const float* __restrict__ e,
                const float* __restrict__ rhs,
                const float* __restrict__ cx,
                const float* __restrict__ cy,
                float* __restrict__ udst, int n, float ih2) {
    __shared__ float pool[2548];
    pjj_tile(u, e, rhs, cx, cy, udst, n, ih2,
             blockIdx.x * 64, blockIdx.y * 16, threadIdx.x, pool);
}

__global__ __launch_bounds__(256)
void jrr2_kernel(const float* __restrict__ u,
                 const float* __restrict__ rhs,
                 const float* __restrict__ cx,
                 const float* __restrict__ cy,
                 float* __restrict__ udst,
                 float* __restrict__ rc, int n, float ih2) {
    __shared__ float s1[20 * 68];
    __shared__ float su[18 * 66];
    const int tid = threadIdx.x;
    const int tx = tid & 31, ty = tid >> 5;
    const int bx0 = blockIdx.x * 64, by0 = blockIdx.y * 16;

    for (int sp = tid; sp < 20 * 68; sp += 256) {
        int py = sp / 68, px = sp % 68;
        int gy = by0 + py - 2, gx = bx0 + px - 2;
        float v = 0.0f;
        if ((unsigned)gy < (unsigned)n && (unsigned)gx < (unsigned)n)
            v = jac_pt(u, rhs, cx, cy, gy, gx, n, ih2);
        s1[sp] = v;
    }
    __syncthreads();

    for (int sp = tid; sp < 18 * 66; sp += 256) {
        int py = sp / 66, px = sp % 66;
        int gy = by0 + py - 1, gx = bx0 + px - 1;
        float v = 0.0f;
        if ((unsigned)gy < (unsigned)n && (unsigned)gx < (unsigned)n)
            v = jac_sm(s1, py + 1, px + 1, 68, rhs, cx, cy, gy, gx, n, ih2);
        su[sp] = v;
    }
    __syncthreads();

    const int gx0 = bx0 + 2 * tx, gy0 = by0 + 2 * ty;
    const int lx0 = 2 * tx + 1, ly0 = 2 * ty + 1;

    *reinterpret_cast<float2*>(&udst[gy0 * n + gx0]) =
        make_float2(su[ly0 * 66 + lx0], su[ly0 * 66 + lx0 + 1]);
    *reinterpret_cast<float2*>(&udst[(gy0 + 1) * n + gx0]) =
        make_float2(su[(ly0 + 1) * 66 + lx0], su[(ly0 + 1) * 66 + lx0 + 1]);

    float s = resid_sm(su, ly0, lx0, 66, rhs, cx, cy, gy0, gx0, n, ih2) +
              resid_sm(su, ly0, lx0 + 1, 66, rhs, cx, cy, gy0, gx0 + 1, n, ih2) +
              resid_sm(su, ly0 + 1, lx0, 66, rhs, cx, cy, gy0 + 1, gx0, n, ih2) +
              resid_sm(su, ly0 + 1, lx0 + 1, 66, rhs, cx, cy, gy0 + 1, gx0 + 1, n, ih2);
    int nc = n >> 1;
    rc[((by0 >> 1) + ty) * nc + (bx0 >> 1) + tx] = 0.25f * s;
}

// ===========================================================================
// l3_stage (R8, correctness-verified): 256 CTAs, owned 16x16, halo 11,
// active 38x38 (stride 40), coeffs in registers, SMEM ping-pong,
// internal grid barrier at sweep 11. pool >= 3040 floats.
// ===========================================================================
__device__ void l3_stage(const float* __restrict__ r3,
                         const float* __restrict__ cx3,
                         const float* __restrict__ cy3,
                         float* __restrict__ umid,
                         float* __restrict__ uout,
                         int tid, int b, float* pool) {
    float* ua = pool;
    float* ub = pool + 1520;      // 38*40
    const int gx0 = (b & 15) * 16 - 11;
    const int gy0 = (b >> 4) * 16 - 11;
    const float ih2 = 0.015625f;

    int pidx[6];
    float cae[6], caw[6], can[6], cas[6], cb[6], cu[6];
#pragma unroll
    for (int i = 0; i < 6; ++i) {
        int q = tid + 256 * i;
        pidx[i] = -1;
        cae[i] = caw[i] = can[i] = cas[i] = cb[i] = cu[i] = 0.0f;
        if (q < 36 * 36) {
            int py = q / 36 + 1, px = q % 36 + 1;
            pidx[i] = py * 40 + px;
            int gy = gy0 + py, gx = gx0 + px;
            if ((unsigned)gy < (unsigned)N3 && (unsigned)gx < (unsigned)N3) {
                int idx = gy * N3 + gx;
                float cxe = cx3[idx];
                float cxw = (gx > 0) ? cx3[idx - 1] : 0.0f;
                float cyn = cy3[idx];
                float cys = (gy > 0) ? cy3[idx - N3] : 0.0f;
                float wv = __fdividef(OMEGA_W,
                                      -((cxe + cxw) + (cyn + cys)) * ih2 - 1.0f);
                float wi = wv * ih2;
                cae[i] = wi * cxe; caw[i] = wi * cxw;
                can[i] = wi * cyn; cas[i] = wi * cys;
                cb[i] = wv * r3[idx];
            }
        }
    }

    for (int sp = tid; sp < 2 * 1520; sp += 256) pool[sp] = 0.0f;
    __syncthreads();

    float* src = ua;
    float* dst = ub;
#pragma unroll 1
    for (int k = 0; k < 11; ++k) {
#pragma unroll
        for (int i = 0; i < 6; ++i) {
            int p = pidx[i];
            if (p >= 0) {
                float v = (1.0f - OMEGA_W) * cu[i] + cb[i] -
                          (cae[i] * src[p + 1] + caw[i] * src[p - 1] +
                           can[i] * src[p + 40] + cas[i] * src[p - 40]);
                dst[p] = v;
                cu[i] = v;
            }
        }
        __syncthreads();
        float* t = src; src = dst; dst = t;
    }

    {
        int py = 11 + (tid >> 4), px = 11 + (tid & 15);
        umid[(gy0 + py) * N3 + (gx0 + px)] = src[py * 40 + px];
    }
    grid_barrier_256();

    for (int sp = tid; sp < 38 * 38; sp += 256) {
        int py = sp / 38, px = sp % 38;
        int p = py * 40 + px;
        int gy = gy0 + py, gx = gx0 + px;
        float v = 0.0f;
        if ((unsigned)gy < (unsigned)N3 && (unsigned)gx < (unsigned)N3)
            v = umid[gy * N3 + gx];
        ua[p] = v; ub[p] = v;
    }
    __syncthreads();
#pragma unroll
    for (int i = 0; i < 6; ++i)
        if (pidx[i] >= 0) cu[i] = ua[pidx[i]];

    src = ua; dst = ub;
#pragma unroll 1
    for (int k = 0; k < 11; ++k) {
#pragma unroll
        for (int i = 0; i < 6; ++i) {
            int p = pidx[i];
            if (p >= 0) {
                float v = (1.0f - OMEGA_W) * cu[i] + cb[i] -
                          (cae[i] * src[p + 1] + caw[i] * src[p - 1] +
                           can[i] * src[p + 40] + cas[i] * src[p - 40]);
                dst[p] = v;
                cu[i] = v;
            }
        }
        __syncthreads();
        float* t = src; src = dst; dst = t;
    }

    {
        int py = 11 + (tid >> 4), px = 11 + (tid & 15);
        uout[(gy0 + py) * N3 + (gx0 + px)] = src[py * 40 + px];
    }
}

// ===========================================================================
// mid_kernel: L2-pre -> L3 (22 sweeps) -> L2-post in ONE persistent launch.
// 256 CTAs x 256 threads (1 L2 tile per CTA at each stage — no serialization).
// ===========================================================================
__global__ __launch_bounds__(256, 2)
void mid_kernel(const float* __restrict__ r2,
                const float* __restrict__ cx2, const float* __restrict__ cy2,
                float* __restrict__ u2a, float* __restrict__ r3,
                const float* __restrict__ cx3, const float* __restrict__ cy3,
                float* __restrict__ u3mid, float* __restrict__ u3out,
                float* __restrict__ u2b) {
    __shared__ float pool[3040];
    const int tid = threadIdx.x;
    const int b = blockIdx.x;
    const int bx0 = (b & 7) * 64, by0 = (b >> 3) * 16;

    // Stage A: L2 pre-smooth + resid + restrict
    jrr0_tile(r2, cx2, cy2, u2a, r3, N2, 0.0625f, bx0, by0, tid, pool);
    grid_barrier_256();

    // Stage B: L3, all 22 sweeps (internal grid barrier at sweep 11)
    l3_stage(r3, cx3, cy3, u3mid, u3out, tid, b, pool);
    grid_barrier_256();

    // Stage C: L2 correct + post-smooth
    pjj_tile(u2a, u3out, r2, cx2, cy2, u2b, N2, 0.0625f, bx0, by0, tid, pool);
}

// ---------------------------------------------------------------------------
// Host driver: 10 launches.
// ---------------------------------------------------------------------------
extern "C" void kernel_launch(void* const* d_in, const int* in_sizes, int n_in,
                              void* d_out, int out_size) {
    const float* cx[4];
    const float* cy[4];
    const float* rhs;
    if (in_sizes[2] == in_sizes[0]) {
        for (int l = 0; l < 4; ++l) {
            cx[l] = (const float*)d_in[3 * l + 1];
            cy[l] = (const float*)d_in[3 * l + 2];
        }
        rhs = (const float*)d_in[12];
    } else {
        rhs = (const float*)d_in[0];
        for (int l = 0; l < 4; ++l) {
            cx[l] = (const float*)d_in[5 + l];
            cy[l] = (const float*)d_in[9 + l];
        }
    }

    float* uOUT = (float*)d_out;
    float *uB, *uC;
    float *u1a, *u1b, *r1;
    float *u2a, *u2b, *r2;
    float *u3a, *u3b, *r3;
    cudaGetSymbolAddress((void**)&uB, g_u0b);
    cudaGetSymbolAddress((void**)&uC, g_u0c);
    cudaGetSymbolAddress((void**)&u1a, g_u1a);
    cudaGetSymbolAddress((void**)&u1b, g_u1b);
    cudaGetSymbolAddress((void**)&r1, g_r1);
    cudaGetSymbolAddress((void**)&u2a, g_u2a);
    cudaGetSymbolAddress((void**)&u2b, g_u2b);
    cudaGetSymbolAddress((void**)&r2, g_r2);
    cudaGetSymbolAddress((void**)&u3a, g_u3a);
    cudaGetSymbolAddress((void**)&u3b, g_u3b);
    cudaGetSymbolAddress((void**)&r3, g_r3);

    const float ih2_0 = 1.0f, ih2_1 = 0.25f;

    dim3 t0(N0 / 64, N0 / 16);
    dim3 t1(N1 / 64, N1 / 16);

    for (int cyc = 0; cyc < 2; ++cyc) {
        // ----- level 0: pre-smooth (2) + residual + restrict -> r1; u -> uB
        if (cyc == 0) {
            jrr0_kernel<<<t0, 256>>>(rhs, cx[0], cy[0], uB, r1, N0, ih2_0);
        } else {
            jrr2_kernel<<<t0, 256>>>(uC, rhs, cx[0], cy[0], uB, r1, N0, ih2_0);
        }

        // ----- level 1: pre (from zero) + residual + restrict -> r2
        jrr0_kernel<<<t1, 256>>>(r1, cx[1], cy[1], u1a, r2, N1, ih2_1);

        // ----- levels 2..3..2: ONE persistent launch
        mid_kernel<<<256, 256>>>(r2, cx[2], cy[2], u2a, r3,
                                 cx[3], cy[3], u3a, u3b, u2b);

        // ----- level 1: correct + post (2) -> u1b
        pjj_kernel<<<t1, 256>>>(u1a, u2b, r1, cx[1], cy[1], u1b, N1, 0.25f);

        // ----- level 0: correct + post (2)
        if (cyc == 0) {
            pjj_kernel<<<t0, 256>>>(uB, u1b, rhs, cx[0], cy[0], uC, N0, ih2_0);
        } else {
            pjj_kernel<<<t0, 256>>>(uB, u1b, rhs, cx[0], cy[0], uOUT, N0, ih2_0);
        }
    }
}

// round 11
// speedup vs baseline: 1.3646x; 1.1192x over previous
#include <cuda_runtime.h>
#include <cstdint>

#define OMEGA_W 0.9f

#define N0 2048
#define N1 1024
#define N2 512
#define N3 256

// Scratch (device globals — no allocation allowed).
__device__ float g_u0b[N0 * N0];
__device__ float g_u0c[N0 * N0];
__device__ float g_u1a[N1 * N1];
__device__ float g_u1b[N1 * N1];
__device__ float g_r1[N1 * N1];
__device__ float g_u2a[N2 * N2];
__device__ float g_u2b[N2 * N2];
__device__ float g_r2[N2 * N2];
__device__ float g_u3a[N3 * N3];
__device__ float g_u3b[N3 * N3];
__device__ float g_r3[N3 * N3];

// ---------------------------------------------------------------------------
// Checked point helpers (R6, verified).
// ---------------------------------------------------------------------------
__device__ __forceinline__ float jac_pt(const float* __restrict__ u,
                                        const float* __restrict__ rhs,
                                        const float* __restrict__ cx,
                                        const float* __restrict__ cy,
                                        int gy, int gx, int n, float ih2) {
    int idx = gy * n + gx;
    float um = u[idx];
    float ue = (gx + 1 < n) ? u[idx + 1] : 0.0f;
    float uw = (gx > 0) ? u[idx - 1] : 0.0f;
    float uN = (gy + 1 < n) ? u[idx + n] : 0.0f;
    float uS = (gy > 0) ? u[idx - n] : 0.0f;
    float cxe = cx[idx];
    float cxw = (gx > 0) ? cx[idx - 1] : 0.0f;
    float cyn = cy[idx];
    float cys = (gy > 0) ? cy[idx - n] : 0.0f;
    float lap = (cxe * (ue - um) - cxw * (um - uw)) * ih2 +
                (cyn * (uN - um) - cys * (um - uS)) * ih2;
    float r = rhs[idx] - (lap - um);
    float diag = -((cxe + cxw) + (cyn + cys)) * ih2 - 1.0f;
    return um + __fdividef(OMEGA_W * r, diag);
}

__device__ __forceinline__ float jac_sm(const float* __restrict__ sm,
                                        int ly, int lx, int stride,
                                        const float* __restrict__ rhs,
                                        const float* __restrict__ cx,
                                        const float* __restrict__ cy,
                                        int gy, int gx, int n, float ih2) {
    int lp = ly * stride + lx;
    float um = sm[lp];
    int idx = gy * n + gx;
    float cxe = cx[idx];
    float cxw = (gx > 0) ? cx[idx - 1] : 0.0f;
    float cyn = cy[idx];
    float cys = (gy > 0) ? cy[idx - n] : 0.0f;
    float lap = (cxe * (sm[lp + 1] - um) - cxw * (um - sm[lp - 1])) * ih2 +
                (cyn * (sm[lp + stride] - um) - cys * (um - sm[lp - stride])) * ih2;
    float r = rhs[idx] - (lap - um);
    float diag = -((cxe + cxw) + (cyn + cys)) * ih2 - 1.0f;
    return um + __fdividef(OMEGA_W * r, diag);
}

__device__ __forceinline__ float resid_sm(const float* __restrict__ sm,
                                          int ly, int lx, int stride,
                                          const float* __restrict__ rhs,
                                          const float* __restrict__ cx,
                                          const float* __restrict__ cy,
                                          int gy, int gx, int n, float ih2) {
    int lp = ly * stride + lx;
    float um = sm[lp];
    int idx = gy * n + gx;
    float cxe = cx[idx];
    float cxw = (gx > 0) ? cx[idx - 1] : 0.0f;
    float cyn = cy[idx];
    float cys = (gy > 0) ? cy[idx - n] : 0.0f;
    float lap = (cxe * (sm[lp + 1] - um) - cxw * (um - sm[lp - 1])) * ih2 +
                (cyn * (sm[lp + stride] - um) - cys * (um - sm[lp - stride])) * ih2;
    return rhs[idx] - (lap - um);
}

// ---------------------------------------------------------------------------
// Unchecked (interior) point helpers — direct flat index.
// ---------------------------------------------------------------------------
__device__ __forceinline__ float jac_pt_i(const float* __restrict__ u,
                                          const float* __restrict__ rhs,
                                          const float* __restrict__ cx,
                                          const float* __restrict__ cy,
                                          int idx, int n, float ih2) {
    float um = u[idx];
    float cxe = cx[idx], cxw = cx[idx - 1];
    float cyn = cy[idx], cys = cy[idx - n];
    float lap = (cxe * (u[idx + 1] - um) - cxw * (um - u[idx - 1])) * ih2 +
                (cyn * (u[idx + n] - um) - cys * (um - u[idx - n])) * ih2;
    float r = rhs[idx] - (lap - um);
    float diag = -((cxe + cxw) + (cyn + cys)) * ih2 - 1.0f;
    return um + __fdividef(OMEGA_W * r, diag);
}

__device__ __forceinline__ float jac_sm_i(const float* __restrict__ sm,
                                          int lp, int stride,
                                          const float* __restrict__ rhs,
                                          const float* __restrict__ cx,
                                          const float* __restrict__ cy,
                                          int idx, int n, float ih2) {
    float um = sm[lp];
    float cxe = cx[idx], cxw = cx[idx - 1];
    float cyn = cy[idx], cys = cy[idx - n];
    float lap = (cxe * (sm[lp + 1] - um) - cxw * (um - sm[lp - 1])) * ih2 +
                (cyn * (sm[lp + stride] - um) - cys * (um - sm[lp - stride])) * ih2;
    float r = rhs[idx] - (lap - um);
    float diag = -((cxe + cxw) + (cyn + cys)) * ih2 - 1.0f;
    return um + __fdividef(OMEGA_W * r, diag);
}

__device__ __forceinline__ float resid_sm_i(const float* __restrict__ sm,
                                            int lp, int stride,
                                            const float* __restrict__ rhs,
                                            const float* __restrict__ cx,
                                            const float* __restrict__ cy,
                                            int idx, int n, float ih2) {
    float um = sm[lp];
    float cxe = cx[idx], cxw = cx[idx - 1];
    float cyn = cy[idx], cys = cy[idx - n];
    float lap = (cxe * (sm[lp + 1] - um) - cxw * (um - sm[lp - 1])) * ih2 +
                (cyn * (sm[lp + stride] - um) - cys * (um - sm[lp - stride])) * ih2;
    return rhs[idx] - (lap - um);
}

// ===========================================================================
// Shared tail (phases 2+3) for jrr0/jrr2: jacobi s1(20x68)->su(18x66),
// store u (float2), residual + restrict. Flat sp loops (R6 shape).
// ===========================================================================
template <bool IN>
__device__ __forceinline__ void jrr_tail(const float* __restrict__ s1,
                                         float* __restrict__ su,
                                         const float* __restrict__ rhs,
                                         const float* __restrict__ cx,
                                         const float* __restrict__ cy,
                                         float* __restrict__ udst,
                                         float* __restrict__ rc,
                                         int n, float ih2,
                                         int bx0, int by0, int tid) {
    const int tx = tid & 31, ty = tid >> 5;
    const int base2 = (by0 - 1) * n + (bx0 - 1);

    // phase 2
    for (int sp = tid; sp < 18 * 66; sp += 256) {
        int py = sp / 66;
        if (IN) {
            int idx = base2 + py * (n - 66) + sp;
            int lp = sp + 2 * py + 69;   // (py+1)*68 + (px+1)
            su[sp] = jac_sm_i(s1, lp, 68, rhs, cx, cy, idx, n, ih2);
        } else {
            int px = sp - py * 66;
            int gy = by0 + py - 1, gx = bx0 + px - 1;
            float v = 0.0f;
            if ((unsigned)gy < (unsigned)n && (unsigned)gx < (unsigned)n)
                v = jac_sm(s1, py + 1, px + 1, 68, rhs, cx, cy, gy, gx, n, ih2);
            su[sp] = v;
        }
    }
    __syncthreads();

    // phase 3
    const int gx0 = bx0 + 2 * tx, gy0 = by0 + 2 * ty;
    const int lx0 = 2 * tx + 1, ly0 = 2 * ty + 1;

    *reinterpret_cast<float2*>(&udst[gy0 * n + gx0]) =
        make_float2(su[ly0 * 66 + lx0], su[ly0 * 66 + lx0 + 1]);
    *reinterpret_cast<float2*>(&udst[(gy0 + 1) * n + gx0]) =
        make_float2(su[(ly0 + 1) * 66 + lx0], su[(ly0 + 1) * 66 + lx0 + 1]);

    float s;
    if (IN) {
        int i00 = gy0 * n + gx0;
        int l00 = ly0 * 66 + lx0;
        s = resid_sm_i(su, l00, 66, rhs, cx, cy, i00, n, ih2) +
            resid_sm_i(su, l00 + 1, 66, rhs, cx, cy, i00 + 1, n, ih2) +
            resid_sm_i(su, l00 + 66, 66, rhs, cx, cy, i00 + n, n, ih2) +
            resid_sm_i(su, l00 + 67, 66, rhs, cx, cy, i00 + n + 1, n, ih2);
    } else {
        s = resid_sm(su, ly0, lx0, 66, rhs, cx, cy, gy0, gx0, n, ih2) +
            resid_sm(su, ly0, lx0 + 1, 66, rhs, cx, cy, gy0, gx0 + 1, n, ih2) +
            resid_sm(su, ly0 + 1, lx0, 66, rhs, cx, cy, gy0 + 1, gx0, n, ih2) +
            resid_sm(su, ly0 + 1, lx0 + 1, 66, rhs, cx, cy, gy0 + 1, gx0 + 1, n, ih2);
    }
    int nc = n >> 1;
    rc[((by0 >> 1) + ty) * nc + (bx0 >> 1) + tx] = 0.25f * s;
}

// ===========================================================================
// jrr0: u==0 start.
// ===========================================================================
template <bool IN>
__device__ __forceinline__ void jrr0_body(const float* __restrict__ rhs,
                                          const float* __restrict__ cx,
                                          const float* __restrict__ cy,
                                          float* __restrict__ udst,
                                          float* __restrict__ rc,
                                          int n, float ih2,
                                          int bx0, int by0, int tid,
                                          float* s1, float* su) {
    const int base1 = (by0 - 2) * n + (bx0 - 2);
    for (int sp = tid; sp < 20 * 68; sp += 256) {
        if (IN) {
            int py = sp / 68;
            int idx = base1 + py * (n - 68) + sp;
            float cxe = cx[idx], cxw = cx[idx - 1];
            float cyn = cy[idx], cys = cy[idx - n];
            float diag = -((cxe + cxw) + (cyn + cys)) * ih2 - 1.0f;
            s1[sp] = __fdividef(OMEGA_W * rhs[idx], diag);
        } else {
            int py = sp / 68, px = sp - py * 68;
            int gy = by0 + py - 2, gx = bx0 + px - 2;
            float v = 0.0f;
            if ((unsigned)gy < (unsigned)n && (unsigned)gx < (unsigned)n) {
                int idx = gy * n + gx;
                float cxe = cx[idx];
                float cxw = (gx > 0) ? cx[idx - 1] : 0.0f;
                float cyn = cy[idx];
                float cys = (gy > 0) ? cy[idx - n] : 0.0f;
                float diag = -((cxe + cxw) + (cyn + cys)) * ih2 - 1.0f;
                v = __fdividef(OMEGA_W * rhs[idx], diag);
            }
            s1[sp] = v;
        }
    }
    __syncthreads();
    jrr_tail<IN>(s1, su, rhs, cx, cy, udst, rc, n, ih2, bx0, by0, tid);
}

__global__ __launch_bounds__(256)
void jrr0_kernel(const float* __restrict__ rhs,
                 const float* __restrict__ cx,
                 const float* __restrict__ cy,
                 float* __restrict__ udst,
                 float* __restrict__ rc, int n, float ih2) {
    __shared__ float s1[20 * 68];
    __shared__ float su[18 * 66];
    int bx0 = blockIdx.x * 64, by0 = blockIdx.y * 16;
    if (blockIdx.x > 0 && blockIdx.y > 0 &&
        blockIdx.x < gridDim.x - 1 && blockIdx.y < gridDim.y - 1)
        jrr0_body<true>(rhs, cx, cy, udst, rc, n, ih2, bx0, by0, threadIdx.x, s1, su);
    else
        jrr0_body<false>(rhs, cx, cy, udst, rc, n, ih2, bx0, by0, threadIdx.x, s1, su);
}

// ===========================================================================
// jrr2: nonzero u start.
// ===========================================================================
template <bool IN>
__device__ __forceinline__ void jrr2_body(const float* __restrict__ u,
                                          const float* __restrict__ rhs,
                                          const float* __restrict__ cx,
                                          const float* __restrict__ cy,
                                          float* __restrict__ udst,
                                          float* __restrict__ rc,
                                          int n, float ih2,
                                          int bx0, int by0, int tid,
                                          float* s1, float* su) {
    const int base1 = (by0 - 2) * n + (bx0 - 2);
    for (int sp = tid; sp < 20 * 68; sp += 256) {
        if (IN) {
            int py = sp / 68;
            int idx = base1 + py * (n - 68) + sp;
            s1[sp] = jac_pt_i(u, rhs, cx, cy, idx, n, ih2);
        } else {
            int py = sp / 68, px = sp - py * 68;
            int gy = by0 + py - 2, gx = bx0 + px - 2;
            float v = 0.0f;
            if ((unsigned)gy < (unsigned)n && (unsigned)gx < (unsigned)n)
                v = jac_pt(u, rhs, cx, cy, gy, gx, n, ih2);
            s1[sp] = v;
        }
    }
    __syncthreads();
    jrr_tail<IN>(s1, su, rhs, cx, cy, udst, rc, n, ih2, bx0, by0, tid);
}

__global__ __launch_bounds__(256)
void jrr2_kernel(const float* __restrict__ u,
                 const float* __restrict__ rhs,
                 const float* __restrict__ cx,
                 const float* __restrict__ cy,
                 float* __restrict__ udst,
                 float* __restrict__ rc, int n, float ih2) {
    __shared__ float s1[20 * 68];
    __shared__ float su[18 * 66];
    int bx0 = blockIdx.x * 64, by0 = blockIdx.y * 16;
    if (blockIdx.x > 0 && blockIdx.y > 0 &&
        blockIdx.x < gridDim.x - 1 && blockIdx.y < gridDim.y - 1)
        jrr2_body<true>(u, rhs, cx, cy, udst, rc, n, ih2, bx0, by0, threadIdx.x, s1, su);
    else
        jrr2_body<false>(u, rhs, cx, cy, udst, rc, n, ih2, bx0, by0, threadIdx.x, s1, su);
}

// ===========================================================================
// pjj: {u += prolong(e)} + two Jacobi sweeps.
// ===========================================================================
template <bool IN>
__device__ __forceinline__ void pjj_body(const float* __restrict__ u,
                                         const float* __restrict__ e,
                                         const float* __restrict__ rhs,
                                         const float* __restrict__ cx,
                                         const float* __restrict__ cy,
                                         float* __restrict__ udst,
                                         int n, float ih2,
                                         int bx0, int by0, int tid,
                                         float* s1, float* su) {
    const int tx = tid & 31, ty = tid >> 5;
    const int ncc = n >> 1;
    const int base1 = (by0 - 2) * n + (bx0 - 2);
    const int jb = (by0 - 2) >> 1;   // by0-2 is even (by0 = 16*by)
    const int ib = (bx0 - 2) >> 1;   // bx0-2 is even

    // phase 0: prolong-corrected u -> s1
    for (int sp = tid; sp < 20 * 68; sp += 256) {
        int py = sp / 68, px = sp - py * 68;
        if (IN) {
            int idx = base1 + py * (n - 68) + sp;
            int jc = jb + (py >> 1);
            int sj = (py & 1) ? 1 : -1;
            int ic = ib + (px >> 1);
            int si = (px & 1) ? 1 : -1;
            const float* er = e + jc * ncc;
            const float* erj = e + (jc + sj) * ncc;
            float w = 9.0f * er[ic] + 3.0f * er[ic + si] +
                      3.0f * erj[ic] + erj[ic + si];
            s1[sp] = u[idx] + w * 0.0625f;
        } else {
            int gy = by0 + py - 2, gx = bx0 + px - 2;
            float v = 0.0f;
            if ((unsigned)gy < (unsigned)n && (unsigned)gx < (unsigned)n) {
                int jc = gy >> 1, dj = gy & 1;
                int ic = gx >> 1, di = gx & 1;
                int sj = dj ? 1 : -1;
                int si = di ? 1 : -1;
                bool bi = ((unsigned)(ic + si) < (unsigned)ncc);
                bool bj = ((unsigned)(jc + sj) < (unsigned)ncc);
                float vc = e[jc * ncc + ic];
                float vsi = bi ? e[jc * ncc + ic + si] : 0.0f;
                float vsj = bj ? e[(jc + sj) * ncc + ic] : 0.0f;
                float vd = (bi && bj) ? e[(jc + sj) * ncc + ic + si] : 0.0f;
                float den = 9.0f + 3.0f * (bi ? 1.0f : 0.0f) +
                            3.0f * (bj ? 1.0f : 0.0f) + ((bi && bj) ? 1.0f : 0.0f);
                v = u[gy * n + gx] +
                    __fdividef(9.0f * vc + 3.0f * vsi + 3.0f * vsj + vd, den);
            }
            s1[sp] = v;
        }
    }
    __syncthreads();

    // phase 1: jacobi s1 -> su
    const int base2 = (by0 - 1) * n + (bx0 - 1);
    for (int sp = tid; sp < 18 * 66; sp += 256) {
        int py = sp / 66;
        if (IN) {
            int idx = base2 + py * (n - 66) + sp;
            int lp = sp + 2 * py + 69;
            su[sp] = jac_sm_i(s1, lp, 68, rhs, cx, cy, idx, n, ih2);
        } else {
            int px = sp - py * 66;
            int gy = by0 + py - 1, gx = bx0 + px - 1;
            float v = 0.0f;
            if ((unsigned)gy < (unsigned)n && (unsigned)gx < (unsigned)n)
                v = jac_sm(s1, py + 1, px + 1, 68, rhs, cx, cy, gy, gx, n, ih2);
            su[sp] = v;
        }
    }
    __syncthreads();

    // phase 2: jacobi at owned 2x2 + store
    const int gx0 = bx0 + 2 * tx, gy0 = by0 + 2 * ty;
    const int lx0 = 2 * tx + 1, ly0 = 2 * ty + 1;
    float o00, o01, o10, o11;
    if (IN) {
        int i00 = gy0 * n + gx0;
        int l00 = ly0 * 66 + lx0;
        o00 = jac_sm_i(su, l00, 66, rhs, cx, cy, i00, n, ih2);
        o01 = jac_sm_i(su, l00 + 1, 66, rhs, cx, cy, i00 + 1, n, ih2);
        o10 = jac_sm_i(su, l00 + 66, 66, rhs, cx, cy, i00 + n, n, ih2);
        o11 = jac_sm_i(su, l00 + 67, 66, rhs, cx, cy, i00 + n + 1, n, ih2);
    } else {
        o00 = jac_sm(su, ly0, lx0, 66, rhs, cx, cy, gy0, gx0, n, ih2);
        o01 = jac_sm(su, ly0, lx0 + 1, 66, rhs, cx, cy, gy0, gx0 + 1, n, ih2);
        o10 = jac_sm(su, ly0 + 1, lx0, 66, rhs, cx, cy, gy0 + 1, gx0, n, ih2);
        o11 = jac_sm(su, ly0 + 1, lx0 + 1, 66, rhs, cx, cy, gy0 + 1, gx0 + 1, n, ih2);
    }
    *reinterpret_cast<float2*>(&udst[gy0 * n + gx0]) = make_float2(o00, o01);
    *reinterpret_cast<float2*>(&udst[(gy0 + 1) * n + gx0]) = make_float2(o10, o11);
}

__global__ __launch_bounds__(256)
void pjj_kernel(const float* __restrict__ u,
                const float* __restrict__ e,
                const float* __restrict__ rhs,
                const float* __restrict__ cx,
                const float* __restrict__ cy,
                float* __restrict__ udst, int n, float ih2) {
    __shared__ float s1[20 * 68];
    __shared__ float su[18 * 66];
    int bx0 = blockIdx.x * 64, by0 = blockIdx.y * 16;
    if (blockIdx.x > 0 && blockIdx.y > 0 &&
        blockIdx.x < gridDim.x - 1 && blockIdx.y < gridDim.y - 1)
        pjj_body<true>(u, e, rhs, cx, cy, udst, n, ih2, bx0, by0, threadIdx.x, s1, su);
    else
        pjj_body<false>(u, e, rhs, cx, cy, udst, n, ih2, bx0, by0, threadIdx.x, s1, su);
}

// ===========================================================================
// L3 (R6 l3_kernel, measured 8.8us/launch): 128 CTAs (8x16), 512 threads,
// owned 32x16, halo 11, coeffs in registers, SMEM ping-pong, 11 sweeps.
// ===========================================================================
#define L3S 56

__global__ __launch_bounds__(512)
void l3_kernel(const float* __restrict__ uin,
               const float* __restrict__ r3,
               const float* __restrict__ cx3,
               const float* __restrict__ cy3,
               float* __restrict__ uout, int zero_start) {
    __shared__ float ua[38 * L3S], ub[38 * L3S];
    const int tid = threadIdx.x;
    const int gx0 = blockIdx.x * 32 - 11;
    const int gy0 = blockIdx.y * 16 - 11;
    const float ih2 = 0.015625f;

    int pidx[4];
    float cae[4], caw[4], can[4], cas[4], cb[4], cu[4];
#pragma unroll
    for (int i = 0; i < 4; ++i) {
        int q = tid + 512 * i;
        pidx[i] = -1;
        cae[i] = caw[i] = can[i] = cas[i] = cb[i] = cu[i] = 0.0f;
        if (q < 36 * 52) {
            int py = q / 52 + 1, px = q % 52 + 1;
            pidx[i] = py * L3S + px;
            int gy = gy0 + py, gx = gx0 + px;
            if ((unsigned)gy < (unsigned)N3 && (unsigned)gx < (unsigned)N3) {
                int idx = gy * N3 + gx;
                float cxe = cx3[idx];
                float cxw = (gx > 0) ? cx3[idx - 1] : 0.0f;
                float cyn = cy3[idx];
                float cys = (gy > 0) ? cy3[idx - N3] : 0.0f;
                float wv = __fdividef(OMEGA_W,
                                      -((cxe + cxw) + (cyn + cys)) * ih2 - 1.0f);
                float wi = wv * ih2;
                cae[i] = wi * cxe; caw[i] = wi * cxw;
                can[i] = wi * cyn; cas[i] = wi * cys;
                cb[i] = wv * r3[idx];
            }
        }
    }

    for (int sp = tid; sp < 38 * 54; sp += 512) {
        int py = sp / 54, px = sp % 54;
        int p = py * L3S + px;
        float v = 0.0f;
        if (!zero_start) {
            int gy = gy0 + py, gx = gx0 + px;
            if ((unsigned)gy < (unsigned)N3 && (unsigned)gx < (unsigned)N3)
                v = uin[gy * N3 + gx];
        }
        ua[p] = v; ub[p] = v;
    }
    __syncthreads();
#pragma unroll
    for (int i = 0; i < 4; ++i)
        if (pidx[i] >= 0) cu[i] = ua[pidx[i]];

    float* src = ua;
    float* dst = ub;
#pragma unroll 1
    for (int k = 0; k < 11; ++k) {
#pragma unroll
        for (int i = 0; i < 4; ++i) {
            int p = pidx[i];
            if (p >= 0) {
                float v = (1.0f - OMEGA_W) * cu[i] + cb[i] -
                          (cae[i] * src[p + 1] + caw[i] * src[p - 1] +
                           can[i] * src[p + L3S] + cas[i] * src[p - L3S]);
                dst[p] = v;
                cu[i] = v;
            }
        }
        __syncthreads();
        float* t = src; src = dst; dst = t;
    }

    {
        int py = 11 + (tid >> 5), px = 11 + (tid & 31);
        uout[(gy0 + py) * N3 + (gx0 + px)] = src[py * L3S + px];
    }
}

// ---------------------------------------------------------------------------
// Host driver (R6 structure, verified at 242.2us): 16 launches.
// ---------------------------------------------------------------------------
extern "C" void kernel_launch(void* const* d_in, const int* in_sizes, int n_in,
                              void* d_out, int out_size) {
    const float* cx[4];
    const float* cy[4];
    const float* rhs;
    if (in_sizes[2] == in_sizes[0]) {
        for (int l = 0; l < 4; ++l) {
            cx[l] = (const float*)d_in[3 * l + 1];
            cy[l] = (const float*)d_in[3 * l + 2];
        }
        rhs = (const float*)d_in[12];
    } else {
        rhs = (const float*)d_in[0];
        for (int l = 0; l < 4; ++l) {
            cx[l] = (const float*)d_in[5 + l];
            cy[l] = (const float*)d_in[9 + l];
        }
    }

    float* uOUT = (float*)d_out;
    float *uB, *uC;
    float *u1a, *u1b, *r1;
    float *u2a, *u2b, *r2;
    float *u3a, *u3b, *r3;
    cudaGetSymbolAddress((void**)&uB, g_u0b);
    cudaGetSymbolAddress((void**)&uC, g_u0c);
    cudaGetSymbolAddress((void**)&u1a, g_u1a);
    cudaGetSymbolAddress((void**)&u1b, g_u1b);
    cudaGetSymbolAddress((void**)&r1, g_r1);
    cudaGetSymbolAddress((void**)&u2a, g_u2a);
    cudaGetSymbolAddress((void**)&u2b, g_u2b);
    cudaGetSymbolAddress((void**)&r2, g_r2);
    cudaGetSymbolAddress((void**)&u3a, g_u3a);
    cudaGetSymbolAddress((void**)&u3b, g_u3b);
    cudaGetSymbolAddress((void**)&r3, g_r3);

    const float ih2_0 = 1.0f, ih2_1 = 0.25f, ih2_2 = 0.0625f;

    dim3 t0(N0 / 64, N0 / 16);
    dim3 t1(N1 / 64, N1 / 16);
    dim3 t2(N2 / 64, N2 / 16);
    dim3 g3(8, 16);

    for (int cyc = 0; cyc < 2; ++cyc) {
        // ----- level 0: pre-smooth (2) + residual + restrict -> r1; u -> uB
        if (cyc == 0) {
            jrr0_kernel<<<t0, 256>>>(rhs, cx[0], cy[0], uB, r1, N0, ih2_0);
        } else {
            jrr2_kernel<<<t0, 256>>>(uC, rhs, cx[0], cy[0], uB, r1, N0, ih2_0);
        }

        // ----- level 1: pre (from zero) + residual + restrict -> r2
        jrr0_kernel<<<t1, 256>>>(r1, cx[1], cy[1], u1a, r2, N1, ih2_1);

        // ----- level 2: pre (from zero) + residual + restrict -> r3
        jrr0_kernel<<<t2, 256>>>(r2, cx[2], cy[2], u2a, r3, N2, ih2_2);

        // ----- level 3: 22 sweeps = 2 launches of 11
        l3_kernel<<<g3, 512>>>(r3, r3, cx[3], cy[3], u3a, 1);
        l3_kernel<<<g3, 512>>>(u3a, r3, cx[3], cy[3], u3b, 0);

        // ----- level 2: correct + post (2) -> u2b
        pjj_kernel<<<t2, 256>>>(u2a, u3b, r2, cx[2], cy[2], u2b, N2, ih2_2);

        // ----- level 1: correct + post (2) -> u1b
        pjj_kernel<<<t1, 256>>>(u1a, u2b, r1, cx[1], cy[1], u1b, N1, ih2_1);

        // ----- level 0: correct + post (2)
        if (cyc == 0) {
            pjj_kernel<<<t0, 256>>>(uB, u1b, rhs, cx[0], cy[0], uC, N0, ih2_0);
        } else {
            pjj_kernel<<<t0, 256>>>(uB, u1b, rhs, cx[0], cy[0], uOUT, N0, ih2_0);
        }
    }
}

// round 12
// speedup vs baseline: 1.3690x; 1.0032x over previous
#include <cuda_runtime.h>
#include <cstdint>

#define OMEGA_W 0.9f

#define N0 2048
#define N1 1024
#define N2 512
#define N3 256

// Scratch (device globals — no allocation allowed).
__device__ float g_u0b[N0 * N0];
__device__ float g_u0c[N0 * N0];
__device__ float g_u1a[N1 * N1];
__device__ float g_u1b[N1 * N1];
__device__ float g_r1[N1 * N1];
__device__ float g_u2a[N2 * N2];
__device__ float g_u2b[N2 * N2];
__device__ float g_r2[N2 * N2];
__device__ float g_u3a[N3 * N3];
__device__ float g_u3b[N3 * N3];
__device__ float g_r3[N3 * N3];

// Software grid-barrier ticket counter (monotonic; replay-safe under graphs).
__device__ unsigned int g_l3_bar = 0;

// ---------------------------------------------------------------------------
// Checked point helpers.
// ---------------------------------------------------------------------------
__device__ __forceinline__ float jac_pt(const float* __restrict__ u,
                                        const float* __restrict__ rhs,
                                        const float* __restrict__ cx,
                                        const float* __restrict__ cy,
                                        int gy, int gx, int n, float ih2) {
    int idx = gy * n + gx;
    float um = u[idx];
    float ue = (gx + 1 < n) ? u[idx + 1] : 0.0f;
    float uw = (gx > 0) ? u[idx - 1] : 0.0f;
    float uN = (gy + 1 < n) ? u[idx + n] : 0.0f;
    float uS = (gy > 0) ? u[idx - n] : 0.0f;
    float cxe = cx[idx];
    float cxw = (gx > 0) ? cx[idx - 1] : 0.0f;
    float cyn = cy[idx];
    float cys = (gy > 0) ? cy[idx - n] : 0.0f;
    float lap = (cxe * (ue - um) - cxw * (um - uw)) * ih2 +
                (cyn * (uN - um) - cys * (um - uS)) * ih2;
    float r = rhs[idx] - (lap - um);
    float diag = -((cxe + cxw) + (cyn + cys)) * ih2 - 1.0f;
    return um + __fdividef(OMEGA_W * r, diag);
}

__device__ __forceinline__ float jac_sm(const float* __restrict__ sm,
                                        int ly, int lx, int stride,
                                        const float* __restrict__ rhs,
                                        const float* __restrict__ cx,
                                        const float* __restrict__ cy,
                                        int gy, int gx, int n, float ih2) {
    int lp = ly * stride + lx;
    float um = sm[lp];
    int idx = gy * n + gx;
    float cxe = cx[idx];
    float cxw = (gx > 0) ? cx[idx - 1] : 0.0f;
    float cyn = cy[idx];
    float cys = (gy > 0) ? cy[idx - n] : 0.0f;
    float lap = (cxe * (sm[lp + 1] - um) - cxw * (um - sm[lp - 1])) * ih2 +
                (cyn * (sm[lp + stride] - um) - cys * (um - sm[lp - stride])) * ih2;
    float r = rhs[idx] - (lap - um);
    float diag = -((cxe + cxw) + (cyn + cys)) * ih2 - 1.0f;
    return um + __fdividef(OMEGA_W * r, diag);
}

__device__ __forceinline__ float resid_sm(const float* __restrict__ sm,
                                          int ly, int lx, int stride,
                                          const float* __restrict__ rhs,
                                          const float* __restrict__ cx,
                                          const float* __restrict__ cy,
                                          int gy, int gx, int n, float ih2) {
    int lp = ly * stride + lx;
    float um = sm[lp];
    int idx = gy * n + gx;
    float cxe = cx[idx];
    float cxw = (gx > 0) ? cx[idx - 1] : 0.0f;
    float cyn = cy[idx];
    float cys = (gy > 0) ? cy[idx - n] : 0.0f;
    float lap = (cxe * (sm[lp + 1] - um) - cxw * (um - sm[lp - 1])) * ih2 +
                (cyn * (sm[lp + stride] - um) - cys * (um - sm[lp - stride])) * ih2;
    return rhs[idx] - (lap - um);
}

// ---------------------------------------------------------------------------
// Unchecked (interior) point helpers — direct flat index.
// ---------------------------------------------------------------------------
__device__ __forceinline__ float jac_pt_i(const float* __restrict__ u,
                                          const float* __restrict__ rhs,
                                          const float* __restrict__ cx,
                                          const float* __restrict__ cy,
                                          int idx, int n, float ih2) {
    float um = u[idx];
    float cxe = cx[idx], cxw = cx[idx - 1];
    float cyn = cy[idx], cys = cy[idx - n];
    float lap = (cxe * (u[idx + 1] - um) - cxw * (um - u[idx - 1])) * ih2 +
                (cyn * (u[idx + n] - um) - cys * (um - u[idx - n])) * ih2;
    float r = rhs[idx] - (lap - um);
    float diag = -((cxe + cxw) + (cyn + cys)) * ih2 - 1.0f;
    return um + __fdividef(OMEGA_W * r, diag);
}

__device__ __forceinline__ float jac_sm_i(const float* __restrict__ sm,
                                          int lp, int stride,
                                          const float* __restrict__ rhs,
                                          const float* __restrict__ cx,
                                          const float* __restrict__ cy,
                                          int idx, int n, float ih2) {
    float um = sm[lp];
    float cxe = cx[idx], cxw = cx[idx - 1];
    float cyn = cy[idx], cys = cy[idx - n];
    float lap = (cxe * (sm[lp + 1] - um) - cxw * (um - sm[lp - 1])) * ih2 +
                (cyn * (sm[lp + stride] - um) - cys * (um - sm[lp - stride])) * ih2;
    float r = rhs[idx] - (lap - um);
    float diag = -((cxe + cxw) + (cyn + cys)) * ih2 - 1.0f;
    return um + __fdividef(OMEGA_W * r, diag);
}

__device__ __forceinline__ float resid_sm_i(const float* __restrict__ sm,
                                            int lp, int stride,
                                            const float* __restrict__ rhs,
                                            const float* __restrict__ cx,
                                            const float* __restrict__ cy,
                                            int idx, int n, float ih2) {
    float um = sm[lp];
    float cxe = cx[idx], cxw = cx[idx - 1];
    float cyn = cy[idx], cys = cy[idx - n];
    float lap = (cxe * (sm[lp + 1] - um) - cxw * (um - sm[lp - 1])) * ih2 +
                (cyn * (sm[lp + stride] - um) - cys * (um - sm[lp - stride])) * ih2;
    return rhs[idx] - (lap - um);
}

// ===========================================================================
// Shared tail (phases 2+3) for jrr0/jrr2.
// ===========================================================================
template <bool IN>
__device__ __forceinline__ void jrr_tail(const float* __restrict__ s1,
                                         float* __restrict__ su,
                                         const float* __restrict__ rhs,
                                         const float* __restrict__ cx,
                                         const float* __restrict__ cy,
                                         float* __restrict__ udst,
                                         float* __restrict__ rc,
                                         int n, float ih2,
                                         int bx0, int by0, int tid) {
    const int tx = tid & 31, ty = tid >> 5;
    const int base2 = (by0 - 1) * n + (bx0 - 1);

    for (int sp = tid; sp < 18 * 66; sp += 256) {
        int py = sp / 66;
        if (IN) {
            int idx = base2 + py * (n - 66) + sp;
            int lp = sp + 2 * py + 69;   // (py+1)*68 + (px+1)
            su[sp] = jac_sm_i(s1, lp, 68, rhs, cx, cy, idx, n, ih2);
        } else {
            int px = sp - py * 66;
            int gy = by0 + py - 1, gx = bx0 + px - 1;
            float v = 0.0f;
            if ((unsigned)gy < (unsigned)n && (unsigned)gx < (unsigned)n)
                v = jac_sm(s1, py + 1, px + 1, 68, rhs, cx, cy, gy, gx, n, ih2);
            su[sp] = v;
        }
    }
    __syncthreads();

    const int gx0 = bx0 + 2 * tx, gy0 = by0 + 2 * ty;
    const int lx0 = 2 * tx + 1, ly0 = 2 * ty + 1;

    *reinterpret_cast<float2*>(&udst[gy0 * n + gx0]) =
        make_float2(su[ly0 * 66 + lx0], su[ly0 * 66 + lx0 + 1]);
    *reinterpret_cast<float2*>(&udst[(gy0 + 1) * n + gx0]) =
        make_float2(su[(ly0 + 1) * 66 + lx0], su[(ly0 + 1) * 66 + lx0 + 1]);

    float s;
    if (IN) {
        int i00 = gy0 * n + gx0;
        int l00 = ly0 * 66 + lx0;
        s = resid_sm_i(su, l00, 66, rhs, cx, cy, i00, n, ih2) +
            resid_sm_i(su, l00 + 1, 66, rhs, cx, cy, i00 + 1, n, ih2) +
            resid_sm_i(su, l00 + 66, 66, rhs, cx, cy, i00 + n, n, ih2) +
            resid_sm_i(su, l00 + 67, 66, rhs, cx, cy, i00 + n + 1, n, ih2);
    } else {
        s = resid_sm(su, ly0, lx0, 66, rhs, cx, cy, gy0, gx0, n, ih2) +
            resid_sm(su, ly0, lx0 + 1, 66, rhs, cx, cy, gy0, gx0 + 1, n, ih2) +
            resid_sm(su, ly0 + 1, lx0, 66, rhs, cx, cy, gy0 + 1, gx0, n, ih2) +
            resid_sm(su, ly0 + 1, lx0 + 1, 66, rhs, cx, cy, gy0 + 1, gx0 + 1, n, ih2);
    }
    int nc = n >> 1;
    rc[((by0 >> 1) + ty) * nc + (bx0 >> 1) + tx] = 0.25f * s;
}

// ===========================================================================
// jrr0: u==0 start.
// ===========================================================================
template <bool IN>
__device__ __forceinline__ void jrr0_body(const float* __restrict__ rhs,
                                          const float* __restrict__ cx,
                                          const float* __restrict__ cy,
                                          float* __restrict__ udst,
                                          float* __restrict__ rc,
                                          int n, float ih2,
                                          int bx0, int by0, int tid,
                                          float* s1, float* su) {
    const int base1 = (by0 - 2) * n + (bx0 - 2);
    for (int sp = tid; sp < 20 * 68; sp += 256) {
        if (IN) {
            int py = sp / 68;
            int idx = base1 + py * (n - 68) + sp;
            float cxe = cx[idx], cxw = cx[idx - 1];
            float cyn = cy[idx], cys = cy[idx - n];
            float diag = -((cxe + cxw) + (cyn + cys)) * ih2 - 1.0f;
            s1[sp] = __fdividef(OMEGA_W * rhs[idx], diag);
        } else {
            int py = sp / 68, px = sp - py * 68;
            int gy = by0 + py - 2, gx = bx0 + px - 2;
            float v = 0.0f;
            if ((unsigned)gy < (unsigned)n && (unsigned)gx < (unsigned)n) {
                int idx = gy * n + gx;
                float cxe = cx[idx];
                float cxw = (gx > 0) ? cx[idx - 1] : 0.0f;
                float cyn = cy[idx];
                float cys = (gy > 0) ? cy[idx - n] : 0.0f;
                float diag = -((cxe + cxw) + (cyn + cys)) * ih2 - 1.0f;
                v = __fdividef(OMEGA_W * rhs[idx], diag);
            }
            s1[sp] = v;
        }
    }
    __syncthreads();
    jrr_tail<IN>(s1, su, rhs, cx, cy, udst, rc, n, ih2, bx0, by0, tid);
}

__global__ __launch_bounds__(256)
void jrr0_kernel(const float* __restrict__ rhs,
                 const float* __restrict__ cx,
                 const float* __restrict__ cy,
                 float* __restrict__ udst,
                 float* __restrict__ rc, int n, float ih2) {
    __shared__ float s1[20 * 68];
    __shared__ float su[18 * 66];
    int bx0 = blockIdx.x * 64, by0 = blockIdx.y * 16;
    if (blockIdx.x > 0 && blockIdx.y > 0 &&
        blockIdx.x < gridDim.x - 1 && blockIdx.y < gridDim.y - 1)
        jrr0_body<true>(rhs, cx, cy, udst, rc, n, ih2, bx0, by0, threadIdx.x, s1, su);
    else
        jrr0_body<false>(rhs, cx, cy, udst, rc, n, ih2, bx0, by0, threadIdx.x, s1, su);
}

// ===========================================================================
// jrr2: nonzero u start.
// ===========================================================================
template <bool IN>
__device__ __forceinline__ void jrr2_body(const float* __restrict__ u,
                                          const float* __restrict__ rhs,
                                          const float* __restrict__ cx,
                                          const float* __restrict__ cy,
                                          float* __restrict__ udst,
                                          float* __restrict__ rc,
                                          int n, float ih2,
                                          int bx0, int by0, int tid,
                                          float* s1, float* su) {
    const int base1 = (by0 - 2) * n + (bx0 - 2);
    for (int sp = tid; sp < 20 * 68; sp += 256) {
        if (IN) {
            int py = sp / 68;
            int idx = base1 + py * (n - 68) + sp;
            s1[sp] = jac_pt_i(u, rhs, cx, cy, idx, n, ih2);
        } else {
            int py = sp / 68, px = sp - py * 68;
            int gy = by0 + py - 2, gx = bx0 + px - 2;
            float v = 0.0f;
            if ((unsigned)gy < (unsigned)n && (unsigned)gx < (unsigned)n)
                v = jac_pt(u, rhs, cx, cy, gy, gx, n, ih2);
            s1[sp] = v;
        }
    }
    __syncthreads();
    jrr_tail<IN>(s1, su, rhs, cx, cy, udst, rc, n, ih2, bx0, by0, tid);
}

__global__ __launch_bounds__(256)
void jrr2_kernel(const float* __restrict__ u,
                 const float* __restrict__ rhs,
                 const float* __restrict__ cx,
                 const float* __restrict__ cy,
                 float* __restrict__ udst,
                 float* __restrict__ rc, int n, float ih2) {
    __shared__ float s1[20 * 68];
    __shared__ float su[18 * 66];
    int bx0 = blockIdx.x * 64, by0 = blockIdx.y * 16;
    if (blockIdx.x > 0 && blockIdx.y > 0 &&
        blockIdx.x < gridDim.x - 1 && blockIdx.y < gridDim.y - 1)
        jrr2_body<true>(u, rhs, cx, cy, udst, rc, n, ih2, bx0, by0, threadIdx.x, s1, su);
    else
        jrr2_body<false>(u, rhs, cx, cy, udst, rc, n, ih2, bx0, by0, threadIdx.x, s1, su);
}

// ===========================================================================
// pjj: {u += prolong(e)} + two Jacobi sweeps.
// ===========================================================================
template <bool IN>
__device__ __forceinline__ void pjj_body(const float* __restrict__ u,
                                         const float* __restrict__ e,
                                         const float* __restrict__ rhs,
                                         const float* __restrict__ cx,
                                         const float* __restrict__ cy,
                                         float* __restrict__ udst,
                                         int n, float ih2,
                                         int bx0, int by0, int tid,
                                         float* s1, float* su) {
    const int tx = tid & 31, ty = tid >> 5;
    const int ncc = n >> 1;
    const int base1 = (by0 - 2) * n + (bx0 - 2);
    const int jb = (by0 - 2) >> 1;
    const int ib = (bx0 - 2) >> 1;

    for (int sp = tid; sp < 20 * 68; sp += 256) {
        int py = sp / 68, px = sp - py * 68;
        if (IN) {
            int idx = base1 + py * (n - 68) + sp;
            int jc = jb + (py >> 1);
            int sj = (py & 1) ? 1 : -1;
            int ic = ib + (px >> 1);
            int si = (px & 1) ? 1 : -1;
            const float* er = e + jc * ncc;
            const float* erj = e + (jc + sj) * ncc;
            float w = 9.0f * er[ic] + 3.0f * er[ic + si] +
                      3.0f * erj[ic] + erj[ic + si];
            s1[sp] = u[idx] + w * 0.0625f;
        } else {
            int gy = by0 + py - 2, gx = bx0 + px - 2;
            float v = 0.0f;
            if ((unsigned)gy < (unsigned)n && (unsigned)gx < (unsigned)n) {
                int jc = gy >> 1, dj = gy & 1;
                int ic = gx >> 1, di = gx & 1;
                int sj = dj ? 1 : -1;
                int si = di ? 1 : -1;
                bool bi = ((unsigned)(ic + si) < (unsigned)ncc);
                bool bj = ((unsigned)(jc + sj) < (unsigned)ncc);
                float vc = e[jc * ncc + ic];
                float vsi = bi ? e[jc * ncc + ic + si] : 0.0f;
                float vsj = bj ? e[(jc + sj) * ncc + ic] : 0.0f;
                float vd = (bi && bj) ? e[(jc + sj) * ncc + ic + si] : 0.0f;
                float den = 9.0f + 3.0f * (bi ? 1.0f : 0.0f) +
                            3.0f * (bj ? 1.0f : 0.0f) + ((bi && bj) ? 1.0f : 0.0f);
                v = u[gy * n + gx] +
                    __fdividef(9.0f * vc + 3.0f * vsi + 3.0f * vsj + vd, den);
            }
            s1[sp] = v;
        }
    }
    __syncthreads();

    const int base2 = (by0 - 1) * n + (bx0 - 1);
    for (int sp = tid; sp < 18 * 66; sp += 256) {
        int py = sp / 66;
        if (IN) {
            int idx = base2 + py * (n - 66) + sp;
            int lp = sp + 2 * py + 69;
            su[sp] = jac_sm_i(s1, lp, 68, rhs, cx, cy, idx, n, ih2);
        } else {
            int px = sp - py * 66;
            int gy = by0 + py - 1, gx = bx0 + px - 1;
            float v = 0.0f;
            if ((unsigned)gy < (unsigned)n && (unsigned)gx < (unsigned)n)
                v = jac_sm(s1, py + 1, px + 1, 68, rhs, cx, cy, gy, gx, n, ih2);
            su[sp] = v;
        }
    }
    __syncthreads();

    const int gx0 = bx0 + 2 * tx, gy0 = by0 + 2 * ty;
    const int lx0 = 2 * tx + 1, ly0 = 2 * ty + 1;
    float o00, o01, o10, o11;
    if (IN) {
        int i00 = gy0 * n + gx0;
        int l00 = ly0 * 66 + lx0;
        o00 = jac_sm_i(su, l00, 66, rhs, cx, cy, i00, n, ih2);
        o01 = jac_sm_i(su, l00 + 1, 66, rhs, cx, cy, i00 + 1, n, ih2);
        o10 = jac_sm_i(su, l00 + 66, 66, rhs, cx, cy, i00 + n, n, ih2);
        o11 = jac_sm_i(su, l00 + 67, 66, rhs, cx, cy, i00 + n + 1, n, ih2);
    } else {
        o00 = jac_sm(su, ly0, lx0, 66, rhs, cx, cy, gy0, gx0, n, ih2);
        o01 = jac_sm(su, ly0, lx0 + 1, 66, rhs, cx, cy, gy0, gx0 + 1, n, ih2);
        o10 = jac_sm(su, ly0 + 1, lx0, 66, rhs, cx, cy, gy0 + 1, gx0, n, ih2);
        o11 = jac_sm(su, ly0 + 1, lx0 + 1, 66, rhs, cx, cy, gy0 + 1, gx0 + 1, n, ih2);
    }
    *reinterpret_cast<float2*>(&udst[gy0 * n + gx0]) = make_float2(o00, o01);
    *reinterpret_cast<float2*>(&udst[(gy0 + 1) * n + gx0]) = make_float2(o10, o11);
}

__global__ __launch_bounds__(256)
void pjj_kernel(const float* __restrict__ u,
                const float* __restrict__ e,
                const float* __restrict__ rhs,
                const float* __restrict__ cx,
                const float* __restrict__ cy,
                float* __restrict__ udst, int n, float ih2) {
    __shared__ float s1[20 * 68];
    __shared__ float su[18 * 66];
    int bx0 = blockIdx.x * 64, by0 = blockIdx.y * 16;
    if (blockIdx.x > 0 && blockIdx.y > 0 &&
        blockIdx.x < gridDim.x - 1 && blockIdx.y < gridDim.y - 1)
        pjj_body<true>(u, e, rhs, cx, cy, udst, n, ih2, bx0, by0, threadIdx.x, s1, su);
    else
        pjj_body<false>(u, e, rhs, cx, cy, udst, n, ih2, bx0, by0, threadIdx.x, s1, su);
}

// ===========================================================================
// l3_one (R7/R9 verified, ~15us): all 22 coarsest sweeps in ONE launch.
// 128 CTAs (8x16), 512 threads, owned 32x16, halo 11; coeffs in registers;
// SMEM ping-pong; software grid barrier + halo exchange at sweep 11.
// ===========================================================================
#define L3S 56

__global__ __launch_bounds__(512)
void l3_one_kernel(const float* __restrict__ r3,
                   const float* __restrict__ cx3,
                   const float* __restrict__ cy3,
                   float* __restrict__ umid,
                   float* __restrict__ uout) {
    __shared__ float ua[38 * L3S], ub[38 * L3S];
    const int tid = threadIdx.x;
    const int gx0 = blockIdx.x * 32 - 11;
    const int gy0 = blockIdx.y * 16 - 11;
    const float ih2 = 0.015625f;

    int pidx[4];
    float cae[4], caw[4], can[4], cas[4], cb[4], cu[4];
#pragma unroll
    for (int i = 0; i < 4; ++i) {
        int q = tid + 512 * i;
        pidx[i] = -1;
        cae[i] = caw[i] = can[i] = cas[i] = cb[i] = cu[i] = 0.0f;
        if (q < 36 * 52) {
            int py = q / 52 + 1, px = q % 52 + 1;
            pidx[i] = py * L3S + px;
            int gy = gy0 + py, gx = gx0 + px;
            if ((unsigned)gy < (unsigned)N3 && (unsigned)gx < (unsigned)N3) {
                int idx = gy * N3 + gx;
                float cxe = cx3[idx];
                float cxw = (gx > 0) ? cx3[idx - 1] : 0.0f;
                float cyn = cy3[idx];
                float cys = (gy > 0) ? cy3[idx - N3] : 0.0f;
                float wv = __fdividef(OMEGA_W,
                                      -((cxe + cxw) + (cyn + cys)) * ih2 - 1.0f);
                float wi = wv * ih2;
                cae[i] = wi * cxe; caw[i] = wi * cxw;
                can[i] = wi * cyn; cas[i] = wi * cys;
                cb[i] = wv * r3[idx];
            }
        }
    }

    for (int sp = tid; sp < 38 * L3S; sp += 512) { ua[sp] = 0.0f; ub[sp] = 0.0f; }
    __syncthreads();

    float* src = ua;
    float* dst = ub;
#pragma unroll 1
    for (int k = 0; k < 11; ++k) {
#pragma unroll
        for (int i = 0; i < 4; ++i) {
            int p = pidx[i];
            if (p >= 0) {
                float v = (1.0f - OMEGA_W) * cu[i] + cb[i] -
                          (cae[i] * src[p + 1] + caw[i] * src[p - 1] +
                           can[i] * src[p + L3S] + cas[i] * src[p - L3S]);
                dst[p] = v;
                cu[i] = v;
            }
        }
        __syncthreads();
        float* t = src; src = dst; dst = t;
    }

    {
        int py = 11 + (tid >> 5), px = 11 + (tid & 31);
        umid[(gy0 + py) * N3 + (gx0 + px)] = src[py * L3S + px];
    }
    __threadfence();
    __syncthreads();
    if (tid == 0) {
        unsigned ticket = atomicAdd(&g_l3_bar, 1u);
        unsigned target = (ticket / 128u + 1u) * 128u;
        while (*(volatile unsigned*)&g_l3_bar < target) __nanosleep(128);
    }
    __syncthreads();

    for (int sp = tid; sp < 38 * 54; sp += 512) {
        int py = sp / 54, px = sp % 54;
        int p = py * L3S + px;
        int gy = gy0 + py, gx = gx0 + px;
        float v = 0.0f;
        if ((unsigned)gy < (unsigned)N3 && (unsigned)gx < (unsigned)N3)
            v = umid[gy * N3 + gx];
        ua[p] = v; ub[p] = v;
    }
    __syncthreads();
#pragma unroll
    for (int i = 0; i < 4; ++i)
        if (pidx[i] >= 0) cu[i] = ua[pidx[i]];

    src = ua; dst = ub;
#pragma unroll 1
    for (int k = 0; k < 11; ++k) {
#pragma unroll
        for (int i = 0; i < 4; ++i) {
            int p = pidx[i];
            if (p >= 0) {
                float v = (1.0f - OMEGA_W) * cu[i] + cb[i] -
                          (cae[i] * src[p + 1] + caw[i] * src[p - 1] +
                           can[i] * src[p + L3S] + cas[i] * src[p - L3S]);
                dst[p] = v;
                cu[i] = v;
            }
        }
        __syncthreads();
        float* t = src; src = dst; dst = t;
    }

    {
        int py = 11 + (tid >> 5), px = 11 + (tid & 31);
        uout[(gy0 + py) * N3 + (gx0 + px)] = src[py * L3S + px];
    }
}

// ---------------------------------------------------------------------------
// Host driver: 14 launches.
// ---------------------------------------------------------------------------
extern "C" void kernel_launch(void* const* d_in, const int* in_sizes, int n_in,
                              void* d_out, int out_size) {
    const float* cx[4];
    const float* cy[4];
    const float* rhs;
    if (in_sizes[2] == in_sizes[0]) {
        for (int l = 0; l < 4; ++l) {
            cx[l] = (const float*)d_in[3 * l + 1];
            cy[l] = (const float*)d_in[3 * l + 2];
        }
        rhs = (const float*)d_in[12];
    } else {
        rhs = (const float*)d_in[0];
        for (int l = 0; l < 4; ++l) {
            cx[l] = (const float*)d_in[5 + l];
            cy[l] = (const float*)d_in[9 + l];
        }
    }

    float* uOUT = (float*)d_out;
    float *uB, *uC;
    float *u1a, *u1b, *r1;
    float *u2a, *u2b, *r2;
    float *u3a, *u3b, *r3;
    cudaGetSymbolAddress((void**)&uB, g_u0b);
    cudaGetSymbolAddress((void**)&uC, g_u0c);
    cudaGetSymbolAddress((void**)&u1a, g_u1a);
    cudaGetSymbolAddress((void**)&u1b, g_u1b);
    cudaGetSymbolAddress((void**)&r1, g_r1);
    cudaGetSymbolAddress((void**)&u2a, g_u2a);
    cudaGetSymbolAddress((void**)&u2b, g_u2b);
    cudaGetSymbolAddress((void**)&r2, g_r2);
    cudaGetSymbolAddress((void**)&u3a, g_u3a);
    cudaGetSymbolAddress((void**)&u3b, g_u3b);
    cudaGetSymbolAddress((void**)&r3, g_r3);

    const float ih2_0 = 1.0f, ih2_1 = 0.25f, ih2_2 = 0.0625f;

    dim3 t0(N0 / 64, N0 / 16);
    dim3 t1(N1 / 64, N1 / 16);
    dim3 t2(N2 / 64, N2 / 16);
    dim3 g3(8, 16);

    for (int cyc = 0; cyc < 2; ++cyc) {
        // ----- level 0: pre-smooth (2) + residual + restrict -> r1; u -> uB
        if (cyc == 0) {
            jrr0_kernel<<<t0, 256>>>(rhs, cx[0], cy[0], uB, r1, N0, ih2_0);
        } else {
            jrr2_kernel<<<t0, 256>>>(uC, rhs, cx[0], cy[0], uB, r1, N0, ih2_0);
        }

        // ----- level 1: pre (from zero) + residual + restrict -> r2
        jrr0_kernel<<<t1, 256>>>(r1, cx[1], cy[1], u1a, r2, N1, ih2_1);

        // ----- level 2: pre (from zero) + residual + restrict -> r3
        jrr0_kernel<<<t2, 256>>>(r2, cx[2], cy[2], u2a, r3, N2, ih2_2);

        // ----- level 3: all 22 sweeps in ONE launch
        l3_one_kernel<<<g3, 512>>>(r3, cx[3], cy[3], u3a, u3b);

        // ----- level 2: correct + post (2) -> u2b
        pjj_kernel<<<t2, 256>>>(u2a, u3b, r2, cx[2], cy[2], u2b, N2, ih2_2);

        // ----- level 1: correct + post (2) -> u1b
        pjj_kernel<<<t1, 256>>>(u1a, u2b, r1, cx[1], cy[1], u1b, N1, ih2_1);

        // ----- level 0: correct + post (2)
        if (cyc == 0) {
            pjj_kernel<<<t0, 256>>>(uB, u1b, rhs, cx[0], cy[0], uC, N0, ih2_0);
        } else {
            pjj_kernel<<<t0, 256>>>(uB, u1b, rhs, cx[0], cy[0], uOUT, N0, ih2_0);
        }
    }
}